// round 1
// baseline (speedup 1.0000x reference)
#include <cuda_runtime.h>
#include <cuda_bf16.h>
#include <cstdio>

// Problem constants
#define BB 2
#define LL 1024
#define DD 1024
#define DI 2048
#define DS 16
#define DC 4
#define DTR 64
#define NTOK (BB*LL)          // 2048 tokens

// ---------------- scratch (static device globals; no allocation) -------------
__device__ float g_u    [NTOK * DD];        // rmsnorm1 output
__device__ float g_xz   [NTOK * 2 * DI];    // in_proj output
__device__ float g_xconv[NTOK * DI];        // conv + silu output
__device__ float g_xdbl [NTOK * 96];        // x_proj output (dt_in | B | C)
__device__ float g_dt   [NTOK * DI];        // softplus(dt)
__device__ float g_ymod [NTOK * DI];        // (y + D*x)*silu(z)
__device__ float g_h    [NTOK * DD];        // residual after mixer
__device__ float g_hn   [NTOK * DD];        // rmsnorm2 output
__device__ float g_m1   [NTOK * 4 * DD];    // fc1 output

// ---------------- rmsnorm ----------------------------------------------------
__global__ void rmsnorm_kernel(const float* __restrict__ x,
                               const float* __restrict__ w,
                               float* __restrict__ o)
{
    const int row = blockIdx.x;
    const float* xr = x + (size_t)row * DD;
    float s = 0.f;
    #pragma unroll
    for (int i = threadIdx.x; i < DD; i += 256) {
        float v = xr[i];
        s += v * v;
    }
    // warp reduce
    #pragma unroll
    for (int off = 16; off > 0; off >>= 1)
        s += __shfl_xor_sync(0xffffffffu, s, off);
    __shared__ float red[8];
    int lane = threadIdx.x & 31, warp = threadIdx.x >> 5;
    if (lane == 0) red[warp] = s;
    __syncthreads();
    if (warp == 0) {
        float t = (lane < 8) ? red[lane] : 0.f;
        #pragma unroll
        for (int off = 4; off > 0; off >>= 1)
            t += __shfl_xor_sync(0xffffffffu, t, off);
        if (lane == 0) red[0] = t;
    }
    __syncthreads();
    float scale = rsqrtf(red[0] * (1.0f / DD) + 1e-6f);
    float* orow = o + (size_t)row * DD;
    for (int i = threadIdx.x; i < DD; i += 256)
        orow[i] = w[i] * xr[i] * scale;
}

// ---------------- GEMM: C[M,N] = A[M,K] * W[N,K]^T, fused epilogues ----------
// EPI: 0 store, 1 +bias, 2 silu(acc+bias), 3 softplus(acc+bias),
//      4 +residual, 5 +bias +residual
template<int EPI>
__global__ __launch_bounds__(256)
void gemm_kernel(const float* __restrict__ A, int lda,
                 const float* __restrict__ W, int ldw,
                 const float* __restrict__ bias,
                 const float* __restrict__ R, int ldr,
                 float* __restrict__ C, int ldc,
                 int N, int K)
{
    __shared__ float As[16][132];   // [k][m], padded row (132*4B multiple of 16B)
    __shared__ float Ws[16][132];   // [k][n]

    const int m0 = blockIdx.y * 128;
    const int n0 = blockIdx.x * 128;
    const int t  = threadIdx.x;
    const int lrow = t >> 2;          // 0..63
    const int lk   = (t & 3) << 2;    // 0,4,8,12
    const int ty   = t >> 4;          // 0..15
    const int tx   = t & 15;          // 0..15

    float acc[8][8];
    #pragma unroll
    for (int i = 0; i < 8; i++)
        #pragma unroll
        for (int j = 0; j < 8; j++) acc[i][j] = 0.f;

    for (int k0 = 0; k0 < K; k0 += 16) {
        // A tile: 128 rows x 16 k (M always a multiple of 128 here)
        #pragma unroll
        for (int r = 0; r < 128; r += 64) {
            const float4 v = *reinterpret_cast<const float4*>(
                &A[(size_t)(m0 + lrow + r) * lda + k0 + lk]);
            As[lk + 0][lrow + r] = v.x;
            As[lk + 1][lrow + r] = v.y;
            As[lk + 2][lrow + r] = v.z;
            As[lk + 3][lrow + r] = v.w;
        }
        // W tile: 128 rows x 16 k, guard n < N
        #pragma unroll
        for (int r = 0; r < 128; r += 64) {
            const int n = n0 + lrow + r;
            float4 v = make_float4(0.f, 0.f, 0.f, 0.f);
            if (n < N)
                v = *reinterpret_cast<const float4*>(
                    &W[(size_t)n * ldw + k0 + lk]);
            Ws[lk + 0][lrow + r] = v.x;
            Ws[lk + 1][lrow + r] = v.y;
            Ws[lk + 2][lrow + r] = v.z;
            Ws[lk + 3][lrow + r] = v.w;
        }
        __syncthreads();

        #pragma unroll
        for (int k = 0; k < 16; k++) {
            float a[8], w[8];
            const float4 a0 = *reinterpret_cast<const float4*>(&As[k][ty * 8]);
            const float4 a1 = *reinterpret_cast<const float4*>(&As[k][ty * 8 + 4]);
            const float4 w0 = *reinterpret_cast<const float4*>(&Ws[k][tx * 8]);
            const float4 w1 = *reinterpret_cast<const float4*>(&Ws[k][tx * 8 + 4]);
            a[0]=a0.x; a[1]=a0.y; a[2]=a0.z; a[3]=a0.w;
            a[4]=a1.x; a[5]=a1.y; a[6]=a1.z; a[7]=a1.w;
            w[0]=w0.x; w[1]=w0.y; w[2]=w0.z; w[3]=w0.w;
            w[4]=w1.x; w[5]=w1.y; w[6]=w1.z; w[7]=w1.w;
            #pragma unroll
            for (int i = 0; i < 8; i++)
                #pragma unroll
                for (int j = 0; j < 8; j++)
                    acc[i][j] += a[i] * w[j];
        }
        __syncthreads();
    }

    // epilogue
    #pragma unroll
    for (int i = 0; i < 8; i++) {
        const int m = m0 + ty * 8 + i;
        #pragma unroll
        for (int j = 0; j < 8; j++) {
            const int n = n0 + tx * 8 + j;
            if (n < N) {
                float v = acc[i][j];
                if (EPI == 1 || EPI == 2 || EPI == 3 || EPI == 5) v += bias[n];
                if (EPI == 2) v = v / (1.f + __expf(-v));               // silu
                if (EPI == 3) v = (v > 20.f) ? v : log1pf(__expf(v));   // softplus
                if (EPI == 4 || EPI == 5) v += R[(size_t)m * ldr + n];
                C[(size_t)m * ldc + n] = v;
            }
        }
    }
}

// ---------------- causal depthwise conv (DC=4) + SiLU ------------------------
__global__ void conv_silu_kernel(const float* __restrict__ xz,
                                 const float* __restrict__ cw,
                                 const float* __restrict__ cb,
                                 float* __restrict__ xc)
{
    const int gid = blockIdx.x * blockDim.x + threadIdx.x;
    if (gid >= NTOK * DI) return;
    const int d = gid % DI;
    const int row = gid / DI;          // b*L + l
    const int l = row % LL;
    const int bbase = (row - l) ;      // b*L

    float acc = cb[d];
    #pragma unroll
    for (int k = 0; k < DC; k++) {
        const int ll = l + k - (DC - 1);
        if (ll >= 0)
            acc += cw[d * DC + k] * xz[(size_t)(bbase + ll) * (2 * DI) + d];
    }
    // silu
    xc[gid] = acc / (1.f + __expf(-acc));
}

// ---------------- selective scan ---------------------------------------------
// 4 threads per (b,d) channel; 4 states each; shfl reduce over the quad.
__global__ void scan_kernel(const float* __restrict__ dt,
                            const float* __restrict__ xc,
                            const float* __restrict__ xdbl,
                            const float* __restrict__ xz,
                            const float* __restrict__ A_log,
                            const float* __restrict__ Dp,
                            float* __restrict__ ymod)
{
    const int gtid = blockIdx.x * blockDim.x + threadIdx.x;
    if (gtid >= BB * DI * 4) return;
    const int sub  = gtid & 3;       // which quarter of the 16 states
    const int pair = gtid >> 2;
    const int d = pair & (DI - 1);
    const int b = pair >> 11;        // DI = 2048 = 2^11

    float Aj[4];
    #pragma unroll
    for (int j = 0; j < 4; j++)
        Aj[j] = -expf(A_log[d * DS + sub * 4 + j]);
    float h[4] = {0.f, 0.f, 0.f, 0.f};
    const float Dv = Dp[d];

    for (int l = 0; l < LL; l++) {
        const int row = b * LL + l;
        const float dtv = dt[(size_t)row * DI + d];
        const float xv  = xc[(size_t)row * DI + d];
        const float* xd = xdbl + (size_t)row * 96;
        float y = 0.f;
        #pragma unroll
        for (int j = 0; j < 4; j++) {
            const float Bt = xd[DTR + sub * 4 + j];
            const float Ct = xd[DTR + DS + sub * 4 + j];
            const float dA = __expf(dtv * Aj[j]);
            h[j] = dA * h[j] + dtv * Bt * xv;
            y += h[j] * Ct;
        }
        y += __shfl_xor_sync(0xffffffffu, y, 1);
        y += __shfl_xor_sync(0xffffffffu, y, 2);
        if (sub == 0) {
            const float zv = xz[(size_t)row * (2 * DI) + DI + d];
            const float sz = zv / (1.f + __expf(-zv));
            ymod[(size_t)row * DI + d] = (y + Dv * xv) * sz;
        }
    }
}

// ---------------- launch -----------------------------------------------------
extern "C" void kernel_launch(void* const* d_in, const int* in_sizes, int n_in,
                              void* d_out, int out_size)
{
    const float* hidden    = (const float*)d_in[0];
    const float* norm1_w   = (const float*)d_in[1];
    const float* in_proj_w = (const float*)d_in[2];
    const float* conv_w    = (const float*)d_in[3];
    const float* conv_b    = (const float*)d_in[4];
    const float* x_proj_w  = (const float*)d_in[5];
    const float* dt_proj_w = (const float*)d_in[6];
    const float* dt_proj_b = (const float*)d_in[7];
    const float* A_log     = (const float*)d_in[8];
    const float* D_param   = (const float*)d_in[9];
    const float* out_proj_w= (const float*)d_in[10];
    const float* norm2_w   = (const float*)d_in[11];
    const float* fc1_w     = (const float*)d_in[12];
    const float* fc1_b     = (const float*)d_in[13];
    const float* fc2_w     = (const float*)d_in[14];
    const float* fc2_b     = (const float*)d_in[15];
    float* out = (float*)d_out;

    float *u, *xz, *xc, *xdbl, *dt, *ymod, *h, *hn, *m1;
    cudaGetSymbolAddress((void**)&u,    g_u);
    cudaGetSymbolAddress((void**)&xz,   g_xz);
    cudaGetSymbolAddress((void**)&xc,   g_xconv);
    cudaGetSymbolAddress((void**)&xdbl, g_xdbl);
    cudaGetSymbolAddress((void**)&dt,   g_dt);
    cudaGetSymbolAddress((void**)&ymod, g_ymod);
    cudaGetSymbolAddress((void**)&h,    g_h);
    cudaGetSymbolAddress((void**)&hn,   g_hn);
    cudaGetSymbolAddress((void**)&m1,   g_m1);

    const int MT = NTOK / 128;   // 16 block-rows

    // 1) rmsnorm1
    rmsnorm_kernel<<<NTOK, 256>>>(hidden, norm1_w, u);

    // 2) in_proj: [2048,1024] x [4096,1024]^T -> xz [2048,4096]
    gemm_kernel<0><<<dim3(4096 / 128, MT), 256>>>(u, DD, in_proj_w, DD,
                                                  nullptr, nullptr, 0,
                                                  xz, 2 * DI, 2 * DI, DD);

    // 3) conv + silu
    conv_silu_kernel<<<(NTOK * DI + 255) / 256, 256>>>(xz, conv_w, conv_b, xc);

    // 4) x_proj: [2048,2048] x [96,2048]^T -> xdbl [2048,96]
    gemm_kernel<0><<<dim3(1, MT), 256>>>(xc, DI, x_proj_w, DI,
                                         nullptr, nullptr, 0,
                                         xdbl, 96, 96, DI);

    // 5) dt_proj + softplus: [2048,64](ld 96) x [2048,64]^T -> dt [2048,2048]
    gemm_kernel<3><<<dim3(DI / 128, MT), 256>>>(xdbl, 96, dt_proj_w, DTR,
                                                dt_proj_b, nullptr, 0,
                                                dt, DI, DI, DTR);

    // 6) selective scan + gating -> ymod
    scan_kernel<<<(BB * DI * 4) / 128, 128>>>(dt, xc, xdbl, xz, A_log, D_param, ymod);

    // 7) out_proj + residual(hidden): [2048,2048] x [1024,2048]^T -> h
    gemm_kernel<4><<<dim3(DD / 128, MT), 256>>>(ymod, DI, out_proj_w, DI,
                                                nullptr, hidden, DD,
                                                h, DD, DD, DI);

    // 8) rmsnorm2
    rmsnorm_kernel<<<NTOK, 256>>>(h, norm2_w, hn);

    // 9) fc1 + bias + silu: [2048,1024] x [4096,1024]^T -> m1
    gemm_kernel<2><<<dim3(4 * DD / 128, MT), 256>>>(hn, DD, fc1_w, DD,
                                                    fc1_b, nullptr, 0,
                                                    m1, 4 * DD, 4 * DD, DD);

    // 10) fc2 + bias + residual(h) -> out
    gemm_kernel<5><<<dim3(DD / 128, MT), 256>>>(m1, 4 * DD, fc2_w, 4 * DD,
                                                fc2_b, h, DD,
                                                out, DD, DD, 4 * DD);
}

// round 4
// speedup vs baseline: 1.5426x; 1.5426x over previous
#include <cuda_runtime.h>
#include <cuda_bf16.h>
#include <cstdint>
#include <cstddef>

#define BB 2
#define LL 1024
#define DD 1024
#define DI 2048
#define DS 16
#define DC 4
#define DTR 64
#define NTOK (BB*LL)

// ---------------- scratch (static device globals; no allocation) -------------
__device__ float g_xz  [NTOK*2*DI];
__device__ float g_xc  [NTOK*DI];
__device__ float g_xdbl[NTOK*96];
__device__ float g_dt  [NTOK*DI];
__device__ float g_h   [NTOK*DD];
// bf16 split (hi || lo per row, ld = 2K)
__device__ __nv_bfloat16 g_uS   [NTOK*2*DD];
__device__ __nv_bfloat16 g_xcS  [NTOK*2*DI];
__device__ __nv_bfloat16 g_dtAS [NTOK*2*DTR];
__device__ __nv_bfloat16 g_ymS  [NTOK*2*DI];
__device__ __nv_bfloat16 g_hnS  [NTOK*2*DD];
__device__ __nv_bfloat16 g_m1S  [NTOK*2*4*DD];
__device__ __nv_bfloat16 g_WinS [4096*2*1024];
__device__ __nv_bfloat16 g_WxpS [96*2*2048];
__device__ __nv_bfloat16 g_WdtS [2048*2*64];
__device__ __nv_bfloat16 g_WoutS[1024*2*2048];
__device__ __nv_bfloat16 g_Wfc1S[4096*2*1024];
__device__ __nv_bfloat16 g_Wfc2S[1024*2*4096];

// ---------------- PTX helpers (base PTX only, sm_80+) -------------------------
__device__ __forceinline__ uint32_t smem_u32(const void* p){
    uint32_t a;
    asm("{ .reg .u64 t; cvta.to.shared.u64 t, %1; cvt.u32.u64 %0, t; }" : "=r"(a) : "l"(p));
    return a;
}
__device__ __forceinline__ void cp_async16(uint32_t dst, const void* src, uint32_t sz){
    asm volatile("cp.async.cg.shared.global [%0], [%1], 16, %2;"
                 :: "r"(dst), "l"(src), "r"(sz));
}
__device__ __forceinline__ void cp_commit(){
    asm volatile("cp.async.commit_group;" ::: "memory");
}
__device__ __forceinline__ void cp_wait1(){
    asm volatile("cp.async.wait_group 1;" ::: "memory");
}
__device__ __forceinline__ void ldsm_x4(uint32_t* r, uint32_t addr){
    asm volatile("ldmatrix.sync.aligned.m8n8.x4.shared.b16 {%0,%1,%2,%3}, [%4];"
                 : "=r"(r[0]),"=r"(r[1]),"=r"(r[2]),"=r"(r[3]) : "r"(addr));
}
__device__ __forceinline__ void ldsm_x2(uint32_t* r, uint32_t addr){
    asm volatile("ldmatrix.sync.aligned.m8n8.x2.shared.b16 {%0,%1}, [%2];"
                 : "=r"(r[0]),"=r"(r[1]) : "r"(addr));
}
__device__ __forceinline__ void mma_bf16(float* c, const uint32_t* a, const uint32_t* b){
    asm volatile(
        "mma.sync.aligned.m16n8k16.row.col.f32.bf16.bf16.f32 "
        "{%0,%1,%2,%3}, {%4,%5,%6,%7}, {%8,%9}, {%0,%1,%2,%3};"
        : "+f"(c[0]), "+f"(c[1]), "+f"(c[2]), "+f"(c[3])
        : "r"(a[0]), "r"(a[1]), "r"(a[2]), "r"(a[3]), "r"(b[0]), "r"(b[1]));
}

// swizzled smem offset for row m (128 rows), 16B-quantum q (0..3), 64B rows
// packs 2 rows per 128B line, XORs the 3-bit quantum-in-line with line index.
__device__ __forceinline__ uint32_t sw_off(int m, int q){
    return (uint32_t)(((m >> 1) << 7) + (((((m & 1) << 2) | q) ^ ((m >> 1) & 7)) << 4));
}

// ---------------- mma.sync GEMM: C[M=2048,N] = A[M,K] x W[N,K]^T --------------
// A,Bm: split-bf16 [rows, 2K] (hi||lo); 3-term split product over K' = 3K.
// EPI: 0 none, 2 silu(acc+bias), 3 softplus(acc+bias), 4 +R, 5 +bias +R
#define STG_BYTES 16384
template<int EPI, bool SPLITOUT, bool FP32OUT>
__global__ void __launch_bounds__(256)
gemm_tc(const __nv_bfloat16* __restrict__ A,
        const __nv_bfloat16* __restrict__ Bm,
        int Ktot, int N,
        const float* __restrict__ bias,
        const float* __restrict__ R, int ldr,
        float* __restrict__ C, int ldc,
        __nv_bfloat16* __restrict__ Cs)
{
    __shared__ __align__(128) char smem_buf[3 * STG_BYTES];
    const uint32_t sb = smem_u32(smem_buf);
    const int t = threadIdx.x;
    const int lane = t & 31;
    const int wid = t >> 5;
    const int warp_m = wid & 1;       // 0..1  (64 rows each)
    const int warp_n = wid >> 1;      // 0..3  (32 cols each)
    const int m0 = blockIdx.y * 128;
    const int n0 = blockIdx.x * 128;
    const int ldab = 2 * Ktot;
    const int KS = (3 * Ktot) / 32;   // BK = 32

    // per-lane ldmatrix address components
    const int mat = lane >> 3;        // 0..3
    const int rin = lane & 7;
    const int a_row_base = warp_m * 64 + ((mat & 1) << 3) + rin;
    const int a_qhi = mat >> 1;       // k-block within 16-col step
    const int b_row_base = warp_n * 32 + rin;
    const int b_q = mat & 1;

    float acc[4][4][4];
    #pragma unroll
    for (int i = 0; i < 4; i++)
        #pragma unroll
        for (int j = 0; j < 4; j++)
            #pragma unroll
            for (int c = 0; c < 4; c++) acc[i][j][c] = 0.f;

    auto load_stage = [&](int ks){
        const int kp = ks * 32;
        const int kA = (kp < ldab) ? kp : kp - ldab;   // hi,lo | hi
        const int kB = (kp < Ktot) ? kp : kp - Ktot;   // hi | hi,lo
        const uint32_t aB = sb + (uint32_t)(ks % 3) * STG_BYTES;
        const uint32_t bB = aB + 8192u;
        const __nv_bfloat16* As = A  + (size_t)m0 * ldab + kA;
        const __nv_bfloat16* Bs = Bm + (size_t)n0 * ldab + kB;
        #pragma unroll
        for (int p = 0; p < 2; p++){
            const int e = (p << 8) + t;
            const int r = e >> 2, q = e & 3;
            cp_async16(aB + sw_off(r, q), (const void*)(As + (size_t)r * ldab + q * 8), 16u);
        }
        #pragma unroll
        for (int p = 0; p < 2; p++){
            const int e = (p << 8) + t;
            const int r = e >> 2, q = e & 3;
            const bool ok = (n0 + r) < N;
            const __nv_bfloat16* src = Bs + (size_t)(ok ? r : 0) * ldab + q * 8;
            cp_async16(bB + sw_off(r, q), (const void*)src, ok ? 16u : 0u);
        }
    };

    load_stage(0); cp_commit();
    load_stage(1); cp_commit();

    for (int ks = 0; ks < KS; ks++){
        cp_wait1();
        __syncthreads();
        if (ks + 2 < KS) load_stage(ks + 2);
        cp_commit();

        const uint32_t aB = sb + (uint32_t)(ks % 3) * STG_BYTES;
        const uint32_t bB = aB + 8192u;
        #pragma unroll
        for (int k2 = 0; k2 < 2; k2++){
            uint32_t afr[4][4], bfr[4][2];
            #pragma unroll
            for (int mt = 0; mt < 4; mt++){
                const int m = a_row_base + mt * 16;
                ldsm_x4(afr[mt], aB + sw_off(m, k2 * 2 + a_qhi));
            }
            #pragma unroll
            for (int nt = 0; nt < 4; nt++){
                const int n = b_row_base + nt * 8;
                ldsm_x2(bfr[nt], bB + sw_off(n, k2 * 2 + b_q));
            }
            #pragma unroll
            for (int mt = 0; mt < 4; mt++)
                #pragma unroll
                for (int nt = 0; nt < 4; nt++)
                    mma_bf16(acc[mt][nt], afr[mt], bfr[nt]);
        }
        __syncthreads();
    }

    // ---------------- epilogue (register accumulators -> global) -------------
    const int erow = lane >> 2;           // 0..7
    const int ecol = (lane & 3) << 1;     // 0,2,4,6
    #pragma unroll
    for (int mt = 0; mt < 4; mt++){
        #pragma unroll
        for (int nt = 0; nt < 4; nt++){
            const int n = n0 + warp_n * 32 + nt * 8 + ecol;
            if (n >= N) continue;
            #pragma unroll
            for (int half = 0; half < 2; half++){
                const int m = m0 + warp_m * 64 + mt * 16 + erow + half * 8;
                float v0 = acc[mt][nt][half * 2 + 0];
                float v1 = acc[mt][nt][half * 2 + 1];
                if (EPI == 2 || EPI == 3 || EPI == 5){
                    v0 += bias[n]; v1 += bias[n + 1];
                }
                if (EPI == 2){
                    v0 = v0 / (1.f + __expf(-v0));
                    v1 = v1 / (1.f + __expf(-v1));
                }
                if (EPI == 3){
                    v0 = (v0 > 20.f) ? v0 : log1pf(__expf(v0));
                    v1 = (v1 > 20.f) ? v1 : log1pf(__expf(v1));
                }
                if (EPI == 4 || EPI == 5){
                    const float2 rv = *reinterpret_cast<const float2*>(&R[(size_t)m * ldr + n]);
                    v0 += rv.x; v1 += rv.y;
                }
                if (FP32OUT){
                    float2 o; o.x = v0; o.y = v1;
                    *reinterpret_cast<float2*>(&C[(size_t)m * ldc + n]) = o;
                }
                if (SPLITOUT){
                    __nv_bfloat16 h0 = __float2bfloat16(v0);
                    __nv_bfloat16 h1 = __float2bfloat16(v1);
                    __nv_bfloat162 hh; hh.x = h0; hh.y = h1;
                    __nv_bfloat162 ll;
                    ll.x = __float2bfloat16(v0 - __bfloat162float(h0));
                    ll.y = __float2bfloat16(v1 - __bfloat162float(h1));
                    *reinterpret_cast<__nv_bfloat162*>(&Cs[(size_t)m * (2*N) + n]) = hh;
                    *reinterpret_cast<__nv_bfloat162*>(&Cs[(size_t)m * (2*N) + N + n]) = ll;
                }
            }
        }
    }
}

// ---------------- rmsnorm -> split bf16 --------------------------------------
__global__ void rmsnorm_split_kernel(const float* __restrict__ x,
                                     const float* __restrict__ w,
                                     __nv_bfloat16* __restrict__ o)
{
    const int row = blockIdx.x;
    const float* xr = x + (size_t)row * DD;
    float s = 0.f;
    for (int i = threadIdx.x; i < DD; i += 256) { float v = xr[i]; s += v * v; }
    #pragma unroll
    for (int off = 16; off > 0; off >>= 1) s += __shfl_xor_sync(0xffffffffu, s, off);
    __shared__ float red[8];
    int lane = threadIdx.x & 31, warp = threadIdx.x >> 5;
    if (lane == 0) red[warp] = s;
    __syncthreads();
    if (warp == 0) {
        float tt = (lane < 8) ? red[lane] : 0.f;
        #pragma unroll
        for (int off = 4; off > 0; off >>= 1) tt += __shfl_xor_sync(0xffffffffu, tt, off);
        if (lane == 0) red[0] = tt;
    }
    __syncthreads();
    const float scale = rsqrtf(red[0] * (1.0f / DD) + 1e-6f);
    for (int i = threadIdx.x; i < DD; i += 256) {
        float v = w[i] * xr[i] * scale;
        __nv_bfloat16 hi = __float2bfloat16(v);
        float lo = v - __bfloat162float(hi);
        o[(size_t)row * 2 * DD + i] = hi;
        o[(size_t)row * 2 * DD + DD + i] = __float2bfloat16(lo);
    }
}

// ---------------- conv + silu (fp32 + split out) ------------------------------
__global__ void conv_silu_kernel(const float* __restrict__ xz,
                                 const float* __restrict__ cw,
                                 const float* __restrict__ cb,
                                 float* __restrict__ xc,
                                 __nv_bfloat16* __restrict__ xcS)
{
    const int gid = blockIdx.x * blockDim.x + threadIdx.x;
    if (gid >= NTOK * DI) return;
    const int d = gid % DI;
    const int row = gid / DI;
    const int l = row % LL;
    const int bbase = row - l;
    float acc = cb[d];
    #pragma unroll
    for (int k = 0; k < DC; k++) {
        const int ll = l + k - (DC - 1);
        if (ll >= 0)
            acc += cw[d * DC + k] * xz[(size_t)(bbase + ll) * (2 * DI) + d];
    }
    const float s = acc / (1.f + __expf(-acc));
    xc[gid] = s;
    __nv_bfloat16 hi = __float2bfloat16(s);
    float lo = s - __bfloat162float(hi);
    xcS[(size_t)row * 2 * DI + d] = hi;
    xcS[(size_t)row * 2 * DI + DI + d] = __float2bfloat16(lo);
}

// ---------------- generic fp32 -> split-bf16 converter ------------------------
__global__ void convert_split_kernel(const float* __restrict__ src, int ld, int col0,
                                     int K, __nv_bfloat16* __restrict__ dst, int total)
{
    const int i = blockIdx.x * 256 + threadIdx.x;
    if (i >= total) return;
    const int r = i / K, k = i - r * K;
    const float v = src[(size_t)r * ld + col0 + k];
    __nv_bfloat16 hi = __float2bfloat16(v);
    float lo = v - __bfloat162float(hi);
    dst[(size_t)r * 2 * K + k] = hi;
    dst[(size_t)r * 2 * K + K + k] = __float2bfloat16(lo);
}

// ---------------- selective scan (split out) ----------------------------------
__global__ void scan_kernel(const float* __restrict__ dt,
                            const float* __restrict__ xc,
                            const float* __restrict__ xdbl,
                            const float* __restrict__ xz,
                            const float* __restrict__ A_log,
                            const float* __restrict__ Dp,
                            __nv_bfloat16* __restrict__ ymS)
{
    const int gtid = blockIdx.x * blockDim.x + threadIdx.x;
    if (gtid >= BB * DI * 4) return;
    const int sub  = gtid & 3;
    const int pair = gtid >> 2;
    const int d = pair & (DI - 1);
    const int b = pair >> 11;

    float Aj[4];
    #pragma unroll
    for (int j = 0; j < 4; j++)
        Aj[j] = -expf(A_log[d * DS + sub * 4 + j]);
    float h[4] = {0.f, 0.f, 0.f, 0.f};
    const float Dv = Dp[d];

    for (int l = 0; l < LL; l++) {
        const int row = b * LL + l;
        const float dtv = dt[(size_t)row * DI + d];
        const float xv  = xc[(size_t)row * DI + d];
        const float* xd = xdbl + (size_t)row * 96;
        float y = 0.f;
        #pragma unroll
        for (int j = 0; j < 4; j++) {
            const float Bt = xd[DTR + sub * 4 + j];
            const float Ct = xd[DTR + DS + sub * 4 + j];
            const float dA = __expf(dtv * Aj[j]);
            h[j] = dA * h[j] + dtv * Bt * xv;
            y += h[j] * Ct;
        }
        y += __shfl_xor_sync(0xffffffffu, y, 1);
        y += __shfl_xor_sync(0xffffffffu, y, 2);
        if (sub == 0) {
            const float zv = xz[(size_t)row * (2 * DI) + DI + d];
            const float sz = zv / (1.f + __expf(-zv));
            const float val = (y + Dv * xv) * sz;
            __nv_bfloat16 hi = __float2bfloat16(val);
            float lo = val - __bfloat162float(hi);
            ymS[(size_t)row * 2 * DI + d] = hi;
            ymS[(size_t)row * 2 * DI + DI + d] = __float2bfloat16(lo);
        }
    }
}

// ---------------- launch -------------------------------------------------------
extern "C" void kernel_launch(void* const* d_in, const int* in_sizes, int n_in,
                              void* d_out, int out_size)
{
    const float* hidden    = (const float*)d_in[0];
    const float* norm1_w   = (const float*)d_in[1];
    const float* in_proj_w = (const float*)d_in[2];
    const float* conv_w    = (const float*)d_in[3];
    const float* conv_b    = (const float*)d_in[4];
    const float* x_proj_w  = (const float*)d_in[5];
    const float* dt_proj_w = (const float*)d_in[6];
    const float* dt_proj_b = (const float*)d_in[7];
    const float* A_log     = (const float*)d_in[8];
    const float* D_param   = (const float*)d_in[9];
    const float* out_proj_w= (const float*)d_in[10];
    const float* norm2_w   = (const float*)d_in[11];
    const float* fc1_w     = (const float*)d_in[12];
    const float* fc1_b     = (const float*)d_in[13];
    const float* fc2_w     = (const float*)d_in[14];
    const float* fc2_b     = (const float*)d_in[15];
    float* out = (float*)d_out;

    float *xz, *xc, *xdbl, *dt, *h;
    __nv_bfloat16 *uS, *xcS, *dtAS, *ymS, *hnS, *m1S;
    __nv_bfloat16 *WinS, *WxpS, *WdtS, *WoutS, *Wfc1S, *Wfc2S;
    cudaGetSymbolAddress((void**)&xz,   g_xz);
    cudaGetSymbolAddress((void**)&xc,   g_xc);
    cudaGetSymbolAddress((void**)&xdbl, g_xdbl);
    cudaGetSymbolAddress((void**)&dt,   g_dt);
    cudaGetSymbolAddress((void**)&h,    g_h);
    cudaGetSymbolAddress((void**)&uS,   g_uS);
    cudaGetSymbolAddress((void**)&xcS,  g_xcS);
    cudaGetSymbolAddress((void**)&dtAS, g_dtAS);
    cudaGetSymbolAddress((void**)&ymS,  g_ymS);
    cudaGetSymbolAddress((void**)&hnS,  g_hnS);
    cudaGetSymbolAddress((void**)&m1S,  g_m1S);
    cudaGetSymbolAddress((void**)&WinS, g_WinS);
    cudaGetSymbolAddress((void**)&WxpS, g_WxpS);
    cudaGetSymbolAddress((void**)&WdtS, g_WdtS);
    cudaGetSymbolAddress((void**)&WoutS,g_WoutS);
    cudaGetSymbolAddress((void**)&Wfc1S,g_Wfc1S);
    cudaGetSymbolAddress((void**)&Wfc2S,g_Wfc2S);

    // weight conversions (independent; run first)
    convert_split_kernel<<<(4096*1024+255)/256, 256>>>(in_proj_w, 1024, 0, 1024, WinS, 4096*1024);
    convert_split_kernel<<<(96*2048+255)/256,   256>>>(x_proj_w,  2048, 0, 2048, WxpS, 96*2048);
    convert_split_kernel<<<(2048*64+255)/256,   256>>>(dt_proj_w, 64,   0, 64,   WdtS, 2048*64);
    convert_split_kernel<<<(1024*2048+255)/256, 256>>>(out_proj_w,2048, 0, 2048, WoutS,1024*2048);
    convert_split_kernel<<<(4096*1024+255)/256, 256>>>(fc1_w,     1024, 0, 1024, Wfc1S,4096*1024);
    convert_split_kernel<<<(1024*4096+255)/256, 256>>>(fc2_w,     4096, 0, 4096, Wfc2S,1024*4096);

    // 1) rmsnorm1 -> split u
    rmsnorm_split_kernel<<<NTOK, 256>>>(hidden, norm1_w, uS);

    // 2) in_proj: [2048,1024] x [4096,1024]^T -> xz fp32
    gemm_tc<0,false,true><<<dim3(32,16), 256>>>(
        uS, WinS, 1024, 4096, nullptr, nullptr, 0, xz, 2*DI, nullptr);

    // 3) conv + silu -> xc fp32 + split
    conv_silu_kernel<<<(NTOK*DI+255)/256, 256>>>(xz, conv_w, conv_b, xc, xcS);

    // 4) x_proj: [2048,2048] x [96,2048]^T -> xdbl fp32 (ld 96)
    gemm_tc<0,false,true><<<dim3(1,16), 256>>>(
        xcS, WxpS, 2048, 96, nullptr, nullptr, 0, xdbl, 96, nullptr);

    // 4b) split the dt_in columns of xdbl
    convert_split_kernel<<<(NTOK*DTR+255)/256, 256>>>(xdbl, 96, 0, DTR, dtAS, NTOK*DTR);

    // 5) dt_proj + softplus(+bias): [2048,64] x [2048,64]^T -> dt fp32
    gemm_tc<3,false,true><<<dim3(16,16), 256>>>(
        dtAS, WdtS, 64, 2048, dt_proj_b, nullptr, 0, dt, DI, nullptr);

    // 6) selective scan + gating -> ymod split
    scan_kernel<<<(BB*DI*4)/128, 128>>>(dt, xc, xdbl, xz, A_log, D_param, ymS);

    // 7) out_proj + residual(hidden): [2048,2048] x [1024,2048]^T -> h fp32
    gemm_tc<4,false,true><<<dim3(8,16), 256>>>(
        ymS, WoutS, 2048, 1024, nullptr, hidden, DD, h, DD, nullptr);

    // 8) rmsnorm2 -> split hn
    rmsnorm_split_kernel<<<NTOK, 256>>>(h, norm2_w, hnS);

    // 9) fc1 + bias + silu -> m1 split only
    gemm_tc<2,true,false><<<dim3(32,16), 256>>>(
        hnS, Wfc1S, 1024, 4096, fc1_b, nullptr, 0, nullptr, 0, m1S);

    // 10) fc2 + bias + residual(h) -> out fp32
    gemm_tc<5,false,true><<<dim3(8,16), 256>>>(
        m1S, Wfc2S, 4096, 1024, fc2_b, h, DD, out, DD, nullptr);
}

// round 5
// speedup vs baseline: 2.2963x; 1.4886x over previous
#include <cuda_runtime.h>
#include <cuda_bf16.h>
#include <cstdint>
#include <cstddef>

#define BB 2
#define LL 1024
#define DD 1024
#define DI 2048
#define DS 16
#define DC 4
#define DTR 64
#define NTOK (BB*LL)

// ---------------- scratch (static device globals; no allocation) -------------
__device__ float g_xz  [NTOK*2*DI];
__device__ float g_xc  [NTOK*DI];
__device__ float g_xdbl[NTOK*96];
__device__ float g_dt  [NTOK*DI];
__device__ float g_h   [NTOK*DD];
__device__ float g_part[8*NTOK*1024];       // split-K partials (max: 8x2048x96 / 2x2048x1024)
// bf16 split (hi || lo per row, ld = 2K)
__device__ __nv_bfloat16 g_uS   [NTOK*2*DD];
__device__ __nv_bfloat16 g_xcS  [NTOK*2*DI];
__device__ __nv_bfloat16 g_dtAS [NTOK*2*DTR];
__device__ __nv_bfloat16 g_ymS  [NTOK*2*DI];
__device__ __nv_bfloat16 g_hnS  [NTOK*2*DD];
__device__ __nv_bfloat16 g_m1S  [NTOK*2*4*DD];
__device__ __nv_bfloat16 g_WinS [4096*2*1024];
__device__ __nv_bfloat16 g_WxpS [96*2*2048];
__device__ __nv_bfloat16 g_WdtS [2048*2*64];
__device__ __nv_bfloat16 g_WoutS[1024*2*2048];
__device__ __nv_bfloat16 g_Wfc1S[4096*2*1024];
__device__ __nv_bfloat16 g_Wfc2S[1024*2*4096];

// ---------------- PTX helpers (base PTX only, sm_80+) -------------------------
__device__ __forceinline__ uint32_t smem_u32(const void* p){
    uint32_t a;
    asm("{ .reg .u64 t; cvta.to.shared.u64 t, %1; cvt.u32.u64 %0, t; }" : "=r"(a) : "l"(p));
    return a;
}
__device__ __forceinline__ void cp_async16(uint32_t dst, const void* src, uint32_t sz){
    asm volatile("cp.async.cg.shared.global [%0], [%1], 16, %2;"
                 :: "r"(dst), "l"(src), "r"(sz));
}
__device__ __forceinline__ void cp_commit(){
    asm volatile("cp.async.commit_group;" ::: "memory");
}
__device__ __forceinline__ void cp_wait1(){
    asm volatile("cp.async.wait_group 1;" ::: "memory");
}
__device__ __forceinline__ void ldsm_x4(uint32_t* r, uint32_t addr){
    asm volatile("ldmatrix.sync.aligned.m8n8.x4.shared.b16 {%0,%1,%2,%3}, [%4];"
                 : "=r"(r[0]),"=r"(r[1]),"=r"(r[2]),"=r"(r[3]) : "r"(addr));
}
__device__ __forceinline__ void ldsm_x2(uint32_t* r, uint32_t addr){
    asm volatile("ldmatrix.sync.aligned.m8n8.x2.shared.b16 {%0,%1}, [%2];"
                 : "=r"(r[0]),"=r"(r[1]) : "r"(addr));
}
__device__ __forceinline__ void mma_bf16(float* c, const uint32_t* a, const uint32_t* b){
    asm volatile(
        "mma.sync.aligned.m16n8k16.row.col.f32.bf16.bf16.f32 "
        "{%0,%1,%2,%3}, {%4,%5,%6,%7}, {%8,%9}, {%0,%1,%2,%3};"
        : "+f"(c[0]), "+f"(c[1]), "+f"(c[2]), "+f"(c[3])
        : "r"(a[0]), "r"(a[1]), "r"(a[2]), "r"(a[3]), "r"(b[0]), "r"(b[1]));
}
// swizzled smem offset: 64B rows, 2 rows per 128B line, XOR quantum with line idx
__device__ __forceinline__ uint32_t sw_off(int m, int q){
    return (uint32_t)(((m >> 1) << 7) + (((((m & 1) << 2) | q) ^ ((m >> 1) & 7)) << 4));
}
// split-K aware 3-term k mapping: seg0 hi*hi, seg1 lo*hi, seg2 hi*lo
__device__ __forceinline__ void seg_k(int ks, int stepsPerSeg, int kc, int Ktot,
                                      int& kA, int& kB){
    const int seg = ks / stepsPerSeg;
    const int off = (ks - seg * stepsPerSeg) * 32 + kc;
    kA = (seg == 1) ? (Ktot + off) : off;
    kB = (seg == 2) ? (Ktot + off) : off;
}

// ---------------- mma.sync GEMM 128x128 tile (split-K capable) ----------------
// EPI: 0 none, 2 silu(+bias), 3 softplus(+bias), 4 +R, 5 +bias +R
#define STG_BYTES 16384
template<int EPI, bool SPLITOUT, bool FP32OUT>
__global__ void __launch_bounds__(256)
gemm_tc(const __nv_bfloat16* __restrict__ A,
        const __nv_bfloat16* __restrict__ Bm,
        int Ktot, int Ksub, int N,
        const float* __restrict__ bias,
        const float* __restrict__ R, int ldr,
        float* __restrict__ C, int ldc,
        __nv_bfloat16* __restrict__ Cs)
{
    __shared__ __align__(128) char smem_buf[3 * STG_BYTES];
    const uint32_t sb = smem_u32(smem_buf);
    const int t = threadIdx.x;
    const int lane = t & 31;
    const int wid = t >> 5;
    const int warp_m = wid & 1;
    const int warp_n = wid >> 1;
    const int m0 = blockIdx.y * 128;
    const int n0 = blockIdx.x * 128;
    const int kc = blockIdx.z * Ksub;
    C += (size_t)blockIdx.z * NTOK * ldc;
    const int ldab = 2 * Ktot;
    const int stepsPerSeg = Ksub / 32;
    const int KS = 3 * stepsPerSeg;

    const int mat = lane >> 3;
    const int rin = lane & 7;
    const int a_row_base = warp_m * 64 + ((mat & 1) << 3) + rin;
    const int a_qhi = mat >> 1;
    const int b_row_base = warp_n * 32 + rin;
    const int b_q = mat & 1;

    float acc[4][4][4];
    #pragma unroll
    for (int i = 0; i < 4; i++)
        #pragma unroll
        for (int j = 0; j < 4; j++)
            #pragma unroll
            for (int c = 0; c < 4; c++) acc[i][j][c] = 0.f;

    auto load_stage = [&](int ks){
        int kA, kB; seg_k(ks, stepsPerSeg, kc, Ktot, kA, kB);
        const uint32_t aB = sb + (uint32_t)(ks % 3) * STG_BYTES;
        const uint32_t bB = aB + 8192u;
        const __nv_bfloat16* As = A  + (size_t)m0 * ldab + kA;
        const __nv_bfloat16* Bs = Bm + (size_t)n0 * ldab + kB;
        #pragma unroll
        for (int p = 0; p < 2; p++){
            const int e = (p << 8) + t;
            const int r = e >> 2, q = e & 3;
            cp_async16(aB + sw_off(r, q), (const void*)(As + (size_t)r * ldab + q * 8), 16u);
        }
        #pragma unroll
        for (int p = 0; p < 2; p++){
            const int e = (p << 8) + t;
            const int r = e >> 2, q = e & 3;
            const bool ok = (n0 + r) < N;
            const __nv_bfloat16* src = Bs + (size_t)(ok ? r : 0) * ldab + q * 8;
            cp_async16(bB + sw_off(r, q), (const void*)src, ok ? 16u : 0u);
        }
    };

    load_stage(0); cp_commit();
    load_stage(1); cp_commit();

    for (int ks = 0; ks < KS; ks++){
        cp_wait1();
        __syncthreads();
        if (ks + 2 < KS) load_stage(ks + 2);
        cp_commit();

        const uint32_t aB = sb + (uint32_t)(ks % 3) * STG_BYTES;
        const uint32_t bB = aB + 8192u;
        #pragma unroll
        for (int k2 = 0; k2 < 2; k2++){
            uint32_t afr[4][4], bfr[4][2];
            #pragma unroll
            for (int mt = 0; mt < 4; mt++)
                ldsm_x4(afr[mt], aB + sw_off(a_row_base + mt * 16, k2 * 2 + a_qhi));
            #pragma unroll
            for (int nt = 0; nt < 4; nt++)
                ldsm_x2(bfr[nt], bB + sw_off(b_row_base + nt * 8, k2 * 2 + b_q));
            #pragma unroll
            for (int mt = 0; mt < 4; mt++)
                #pragma unroll
                for (int nt = 0; nt < 4; nt++)
                    mma_bf16(acc[mt][nt], afr[mt], bfr[nt]);
        }
        __syncthreads();
    }

    const int erow = lane >> 2;
    const int ecol = (lane & 3) << 1;
    #pragma unroll
    for (int mt = 0; mt < 4; mt++){
        #pragma unroll
        for (int nt = 0; nt < 4; nt++){
            const int n = n0 + warp_n * 32 + nt * 8 + ecol;
            if (n >= N) continue;
            #pragma unroll
            for (int half = 0; half < 2; half++){
                const int m = m0 + warp_m * 64 + mt * 16 + erow + half * 8;
                float v0 = acc[mt][nt][half * 2 + 0];
                float v1 = acc[mt][nt][half * 2 + 1];
                if (EPI == 2 || EPI == 3 || EPI == 5){ v0 += bias[n]; v1 += bias[n + 1]; }
                if (EPI == 2){
                    v0 = v0 / (1.f + __expf(-v0)); v1 = v1 / (1.f + __expf(-v1));
                }
                if (EPI == 3){
                    v0 = (v0 > 20.f) ? v0 : log1pf(__expf(v0));
                    v1 = (v1 > 20.f) ? v1 : log1pf(__expf(v1));
                }
                if (EPI == 4 || EPI == 5){
                    const float2 rv = *reinterpret_cast<const float2*>(&R[(size_t)m * ldr + n]);
                    v0 += rv.x; v1 += rv.y;
                }
                if (FP32OUT){
                    float2 o; o.x = v0; o.y = v1;
                    *reinterpret_cast<float2*>(&C[(size_t)m * ldc + n]) = o;
                }
                if (SPLITOUT){
                    __nv_bfloat16 h0 = __float2bfloat16(v0);
                    __nv_bfloat16 h1 = __float2bfloat16(v1);
                    __nv_bfloat162 hh; hh.x = h0; hh.y = h1;
                    __nv_bfloat162 ll;
                    ll.x = __float2bfloat16(v0 - __bfloat162float(h0));
                    ll.y = __float2bfloat16(v1 - __bfloat162float(h1));
                    *reinterpret_cast<__nv_bfloat162*>(&Cs[(size_t)m * (2*N) + n]) = hh;
                    *reinterpret_cast<__nv_bfloat162*>(&Cs[(size_t)m * (2*N) + N + n]) = ll;
                }
            }
        }
    }
}

// ---------------- mma.sync GEMM 256x128 tile (512 threads, dynamic smem) ------
#define BSTG_BYTES 24576
template<int EPI, bool SPLITOUT, bool FP32OUT>
__global__ void __launch_bounds__(512, 1)
gemm_big(const __nv_bfloat16* __restrict__ A,
         const __nv_bfloat16* __restrict__ Bm,
         int Ktot, int N,
         const float* __restrict__ bias,
         const float* __restrict__ R, int ldr,
         float* __restrict__ C, int ldc,
         __nv_bfloat16* __restrict__ Cs)
{
    extern __shared__ __align__(128) char dsmem[];
    const uint32_t sb = smem_u32(dsmem);
    const int t = threadIdx.x;
    const int lane = t & 31;
    const int wid = t >> 5;
    const int warp_m = wid & 3;        // 4 x 64 rows
    const int warp_n = wid >> 2;       // 4 x 32 cols
    const int m0 = blockIdx.y * 256;
    const int n0 = blockIdx.x * 128;
    const int ldab = 2 * Ktot;
    const int stepsPerSeg = Ktot / 32;
    const int KS = 3 * stepsPerSeg;

    const int mat = lane >> 3;
    const int rin = lane & 7;
    const int a_row_base = warp_m * 64 + ((mat & 1) << 3) + rin;
    const int a_qhi = mat >> 1;
    const int b_row_base = warp_n * 32 + rin;
    const int b_q = mat & 1;

    float acc[4][4][4];
    #pragma unroll
    for (int i = 0; i < 4; i++)
        #pragma unroll
        for (int j = 0; j < 4; j++)
            #pragma unroll
            for (int c = 0; c < 4; c++) acc[i][j][c] = 0.f;

    auto load_stage = [&](int ks){
        int kA, kB; seg_k(ks, stepsPerSeg, 0, Ktot, kA, kB);
        const uint32_t aB = sb + (uint32_t)(ks % 3) * BSTG_BYTES;
        const uint32_t bB = aB + 16384u;
        const __nv_bfloat16* As = A  + (size_t)m0 * ldab + kA;
        const __nv_bfloat16* Bs = Bm + (size_t)n0 * ldab + kB;
        #pragma unroll
        for (int p = 0; p < 2; p++){           // A: 256 rows x 4 quanta
            const int e = (p << 9) + t;
            const int r = e >> 2, q = e & 3;
            cp_async16(aB + sw_off(r, q), (const void*)(As + (size_t)r * ldab + q * 8), 16u);
        }
        {                                       // B: 128 rows x 4 quanta
            const int r = t >> 2, q = t & 3;
            const bool ok = (n0 + r) < N;
            const __nv_bfloat16* src = Bs + (size_t)(ok ? r : 0) * ldab + q * 8;
            cp_async16(bB + sw_off(r, q), (const void*)src, ok ? 16u : 0u);
        }
    };

    load_stage(0); cp_commit();
    load_stage(1); cp_commit();

    for (int ks = 0; ks < KS; ks++){
        cp_wait1();
        __syncthreads();
        if (ks + 2 < KS) load_stage(ks + 2);
        cp_commit();

        const uint32_t aB = sb + (uint32_t)(ks % 3) * BSTG_BYTES;
        const uint32_t bB = aB + 16384u;
        #pragma unroll
        for (int k2 = 0; k2 < 2; k2++){
            uint32_t afr[4][4], bfr[4][2];
            #pragma unroll
            for (int mt = 0; mt < 4; mt++)
                ldsm_x4(afr[mt], aB + sw_off(a_row_base + mt * 16, k2 * 2 + a_qhi));
            #pragma unroll
            for (int nt = 0; nt < 4; nt++)
                ldsm_x2(bfr[nt], bB + sw_off(b_row_base + nt * 8, k2 * 2 + b_q));
            #pragma unroll
            for (int mt = 0; mt < 4; mt++)
                #pragma unroll
                for (int nt = 0; nt < 4; nt++)
                    mma_bf16(acc[mt][nt], afr[mt], bfr[nt]);
        }
        __syncthreads();
    }

    const int erow = lane >> 2;
    const int ecol = (lane & 3) << 1;
    #pragma unroll
    for (int mt = 0; mt < 4; mt++){
        #pragma unroll
        for (int nt = 0; nt < 4; nt++){
            const int n = n0 + warp_n * 32 + nt * 8 + ecol;
            if (n >= N) continue;
            #pragma unroll
            for (int half = 0; half < 2; half++){
                const int m = m0 + warp_m * 64 + mt * 16 + erow + half * 8;
                float v0 = acc[mt][nt][half * 2 + 0];
                float v1 = acc[mt][nt][half * 2 + 1];
                if (EPI == 2 || EPI == 3 || EPI == 5){ v0 += bias[n]; v1 += bias[n + 1]; }
                if (EPI == 2){
                    v0 = v0 / (1.f + __expf(-v0)); v1 = v1 / (1.f + __expf(-v1));
                }
                if (EPI == 3){
                    v0 = (v0 > 20.f) ? v0 : log1pf(__expf(v0));
                    v1 = (v1 > 20.f) ? v1 : log1pf(__expf(v1));
                }
                if (EPI == 4 || EPI == 5){
                    const float2 rv = *reinterpret_cast<const float2*>(&R[(size_t)m * ldr + n]);
                    v0 += rv.x; v1 += rv.y;
                }
                if (FP32OUT){
                    float2 o; o.x = v0; o.y = v1;
                    *reinterpret_cast<float2*>(&C[(size_t)m * ldc + n]) = o;
                }
                if (SPLITOUT){
                    __nv_bfloat16 h0 = __float2bfloat16(v0);
                    __nv_bfloat16 h1 = __float2bfloat16(v1);
                    __nv_bfloat162 hh; hh.x = h0; hh.y = h1;
                    __nv_bfloat162 ll;
                    ll.x = __float2bfloat16(v0 - __bfloat162float(h0));
                    ll.y = __float2bfloat16(v1 - __bfloat162float(h1));
                    *reinterpret_cast<__nv_bfloat162*>(&Cs[(size_t)m * (2*N) + n]) = hh;
                    *reinterpret_cast<__nv_bfloat162*>(&Cs[(size_t)m * (2*N) + N + n]) = ll;
                }
            }
        }
    }
}

// ---------------- split-K reduce + fused epilogue ------------------------------
template<int EPI, bool FP32OUT, bool SPLITOUT>
__global__ void reduce_epi(const float* __restrict__ P, int S, int N,
                           const float* __restrict__ bias,
                           const float* __restrict__ R, int ldr,
                           float* __restrict__ C, int ldc,
                           __nv_bfloat16* __restrict__ Cs)
{
    const int i = blockIdx.x * 256 + threadIdx.x;
    const int tot = NTOK * N / 4;
    if (i >= tot) return;
    const int m = (i * 4) / N;
    const int n = (i * 4) - m * N;
    const float4* Pv = reinterpret_cast<const float4*>(P);
    float4 a = Pv[i];
    for (int s = 1; s < S; s++){
        const float4 b = Pv[(size_t)s * tot + i];
        a.x += b.x; a.y += b.y; a.z += b.z; a.w += b.w;
    }
    float v[4] = {a.x, a.y, a.z, a.w};
    if (EPI == 5){
        #pragma unroll
        for (int j = 0; j < 4; j++) v[j] += bias[n + j];
    }
    if (EPI == 4 || EPI == 5){
        const float4 rv = *reinterpret_cast<const float4*>(&R[(size_t)m * ldr + n]);
        v[0] += rv.x; v[1] += rv.y; v[2] += rv.z; v[3] += rv.w;
    }
    if (FP32OUT){
        float4 o; o.x = v[0]; o.y = v[1]; o.z = v[2]; o.w = v[3];
        *reinterpret_cast<float4*>(&C[(size_t)m * ldc + n]) = o;
    }
    if (SPLITOUT){
        #pragma unroll
        for (int j = 0; j < 4; j++){
            __nv_bfloat16 hi = __float2bfloat16(v[j]);
            Cs[(size_t)m * (2*N) + n + j] = hi;
            Cs[(size_t)m * (2*N) + N + n + j] = __float2bfloat16(v[j] - __bfloat162float(hi));
        }
    }
}

// ---------------- rmsnorm -> split bf16 ----------------------------------------
__global__ void rmsnorm_split_kernel(const float* __restrict__ x,
                                     const float* __restrict__ w,
                                     __nv_bfloat16* __restrict__ o)
{
    const int row = blockIdx.x;
    const float* xr = x + (size_t)row * DD;
    float s = 0.f;
    for (int i = threadIdx.x; i < DD; i += 256) { float v = xr[i]; s += v * v; }
    #pragma unroll
    for (int off = 16; off > 0; off >>= 1) s += __shfl_xor_sync(0xffffffffu, s, off);
    __shared__ float red[8];
    int lane = threadIdx.x & 31, warp = threadIdx.x >> 5;
    if (lane == 0) red[warp] = s;
    __syncthreads();
    if (warp == 0) {
        float tt = (lane < 8) ? red[lane] : 0.f;
        #pragma unroll
        for (int off = 4; off > 0; off >>= 1) tt += __shfl_xor_sync(0xffffffffu, tt, off);
        if (lane == 0) red[0] = tt;
    }
    __syncthreads();
    const float scale = rsqrtf(red[0] * (1.0f / DD) + 1e-6f);
    for (int i = threadIdx.x; i < DD; i += 256) {
        float v = w[i] * xr[i] * scale;
        __nv_bfloat16 hi = __float2bfloat16(v);
        o[(size_t)row * 2 * DD + i] = hi;
        o[(size_t)row * 2 * DD + DD + i] = __float2bfloat16(v - __bfloat162float(hi));
    }
}

// ---------------- conv + silu ---------------------------------------------------
__global__ void conv_silu_kernel(const float* __restrict__ xz,
                                 const float* __restrict__ cw,
                                 const float* __restrict__ cb,
                                 float* __restrict__ xc,
                                 __nv_bfloat16* __restrict__ xcS)
{
    const int gid = blockIdx.x * blockDim.x + threadIdx.x;
    if (gid >= NTOK * DI) return;
    const int d = gid % DI;
    const int row = gid / DI;
    const int l = row % LL;
    const int bbase = row - l;
    float acc = cb[d];
    #pragma unroll
    for (int k = 0; k < DC; k++) {
        const int ll = l + k - (DC - 1);
        if (ll >= 0)
            acc += cw[d * DC + k] * xz[(size_t)(bbase + ll) * (2 * DI) + d];
    }
    const float s = acc / (1.f + __expf(-acc));
    xc[gid] = s;
    __nv_bfloat16 hi = __float2bfloat16(s);
    xcS[(size_t)row * 2 * DI + d] = hi;
    xcS[(size_t)row * 2 * DI + DI + d] = __float2bfloat16(s - __bfloat162float(hi));
}

// ---------------- fp32 -> split-bf16 converter ----------------------------------
__global__ void convert_split_kernel(const float* __restrict__ src, int ld, int col0,
                                     int K, __nv_bfloat16* __restrict__ dst, int total)
{
    const int i = blockIdx.x * 256 + threadIdx.x;
    if (i >= total) return;
    const int r = i / K, k = i - r * K;
    const float v = src[(size_t)r * ld + col0 + k];
    __nv_bfloat16 hi = __float2bfloat16(v);
    dst[(size_t)r * 2 * K + k] = hi;
    dst[(size_t)r * 2 * K + K + k] = __float2bfloat16(v - __bfloat162float(hi));
}

// ---------------- selective scan (software pipelined) ---------------------------
__global__ void scan_kernel(const float* __restrict__ dt,
                            const float* __restrict__ xc,
                            const float* __restrict__ xdbl,
                            const float* __restrict__ xz,
                            const float* __restrict__ A_log,
                            const float* __restrict__ Dp,
                            __nv_bfloat16* __restrict__ ymS)
{
    const int gtid = blockIdx.x * blockDim.x + threadIdx.x;
    if (gtid >= BB * DI * 4) return;
    const int sub  = gtid & 3;
    const int pair = gtid >> 2;
    const int d = pair & (DI - 1);
    const int b = pair >> 11;

    float Aj[4];
    #pragma unroll
    for (int j = 0; j < 4; j++)
        Aj[j] = -expf(A_log[d * DS + sub * 4 + j]);
    float h[4] = {0.f, 0.f, 0.f, 0.f};
    const float Dv = Dp[d];

    const float* dtp = dt + (size_t)(b * LL) * DI + d;
    const float* xcp = xc + (size_t)(b * LL) * DI + d;
    const float* xdp = xdbl + (size_t)(b * LL) * 96 + DTR + sub * 4;
    const float* zp  = xz + (size_t)(b * LL) * (2 * DI) + DI + d;
    __nv_bfloat16* yo = ymS + (size_t)(b * LL) * 2 * DI + d;

    // prologue: load l=0, precompute dA
    float dtv = dtp[0];
    float xv  = xcp[0];
    float4 Bv = *reinterpret_cast<const float4*>(xdp);
    float4 Cv = *reinterpret_cast<const float4*>(xdp + DS);
    float zv  = (sub == 0) ? zp[0] : 0.f;
    float dA[4];
    #pragma unroll
    for (int j = 0; j < 4; j++) dA[j] = __expf(dtv * Aj[j]);

    for (int l = 0; l < LL; l++) {
        // prefetch l+1 and precompute its dA (off the h-chain)
        float dtn = 0.f, xn = 0.f, zn = 0.f;
        float4 Bn = make_float4(0.f,0.f,0.f,0.f), Cn = Bn;
        if (l + 1 < LL){
            dtn = dtp[(l + 1) * DI];
            xn  = xcp[(l + 1) * DI];
            Bn  = *reinterpret_cast<const float4*>(xdp + (l + 1) * 96);
            Cn  = *reinterpret_cast<const float4*>(xdp + (l + 1) * 96 + DS);
            if (sub == 0) zn = zp[(l + 1) * 2 * DI];
        }
        float dAn[4];
        #pragma unroll
        for (int j = 0; j < 4; j++) dAn[j] = __expf(dtn * Aj[j]);

        const float dx = dtv * xv;
        const float Bt[4] = {Bv.x, Bv.y, Bv.z, Bv.w};
        const float Ct[4] = {Cv.x, Cv.y, Cv.z, Cv.w};
        float y = 0.f;
        #pragma unroll
        for (int j = 0; j < 4; j++) {
            h[j] = dA[j] * h[j] + dx * Bt[j];
            y += h[j] * Ct[j];
        }
        y += __shfl_xor_sync(0xffffffffu, y, 1);
        y += __shfl_xor_sync(0xffffffffu, y, 2);
        if (sub == 0) {
            const float sz = zv / (1.f + __expf(-zv));
            const float val = (y + Dv * xv) * sz;
            __nv_bfloat16 hi = __float2bfloat16(val);
            yo[(size_t)l * 2 * DI] = hi;
            yo[(size_t)l * 2 * DI + DI] = __float2bfloat16(val - __bfloat162float(hi));
        }
        dtv = dtn; xv = xn; zv = zn; Bv = Bn; Cv = Cn;
        #pragma unroll
        for (int j = 0; j < 4; j++) dA[j] = dAn[j];
    }
}

// ---------------- launch ---------------------------------------------------------
extern "C" void kernel_launch(void* const* d_in, const int* in_sizes, int n_in,
                              void* d_out, int out_size)
{
    const float* hidden    = (const float*)d_in[0];
    const float* norm1_w   = (const float*)d_in[1];
    const float* in_proj_w = (const float*)d_in[2];
    const float* conv_w    = (const float*)d_in[3];
    const float* conv_b    = (const float*)d_in[4];
    const float* x_proj_w  = (const float*)d_in[5];
    const float* dt_proj_w = (const float*)d_in[6];
    const float* dt_proj_b = (const float*)d_in[7];
    const float* A_log     = (const float*)d_in[8];
    const float* D_param   = (const float*)d_in[9];
    const float* out_proj_w= (const float*)d_in[10];
    const float* norm2_w   = (const float*)d_in[11];
    const float* fc1_w     = (const float*)d_in[12];
    const float* fc1_b     = (const float*)d_in[13];
    const float* fc2_w     = (const float*)d_in[14];
    const float* fc2_b     = (const float*)d_in[15];
    float* out = (float*)d_out;

    float *xz, *xc, *xdbl, *dt, *h, *part;
    __nv_bfloat16 *uS, *xcS, *dtAS, *ymS, *hnS, *m1S;
    __nv_bfloat16 *WinS, *WxpS, *WdtS, *WoutS, *Wfc1S, *Wfc2S;
    cudaGetSymbolAddress((void**)&xz,   g_xz);
    cudaGetSymbolAddress((void**)&xc,   g_xc);
    cudaGetSymbolAddress((void**)&xdbl, g_xdbl);
    cudaGetSymbolAddress((void**)&dt,   g_dt);
    cudaGetSymbolAddress((void**)&h,    g_h);
    cudaGetSymbolAddress((void**)&part, g_part);
    cudaGetSymbolAddress((void**)&uS,   g_uS);
    cudaGetSymbolAddress((void**)&xcS,  g_xcS);
    cudaGetSymbolAddress((void**)&dtAS, g_dtAS);
    cudaGetSymbolAddress((void**)&ymS,  g_ymS);
    cudaGetSymbolAddress((void**)&hnS,  g_hnS);
    cudaGetSymbolAddress((void**)&m1S,  g_m1S);
    cudaGetSymbolAddress((void**)&WinS, g_WinS);
    cudaGetSymbolAddress((void**)&WxpS, g_WxpS);
    cudaGetSymbolAddress((void**)&WdtS, g_WdtS);
    cudaGetSymbolAddress((void**)&WoutS,g_WoutS);
    cudaGetSymbolAddress((void**)&Wfc1S,g_Wfc1S);
    cudaGetSymbolAddress((void**)&Wfc2S,g_Wfc2S);

    cudaFuncSetAttribute(gemm_big<0,false,true>, cudaFuncAttributeMaxDynamicSharedMemorySize, 3*BSTG_BYTES);
    cudaFuncSetAttribute(gemm_big<2,true,false>, cudaFuncAttributeMaxDynamicSharedMemorySize, 3*BSTG_BYTES);

    // launches 1-5 (slot 6 = in_proj gemm_big for ncu -s 5 -c 1)
    convert_split_kernel<<<(4096*1024+255)/256, 256>>>(in_proj_w, 1024, 0, 1024, WinS, 4096*1024);
    convert_split_kernel<<<(96*2048+255)/256,   256>>>(x_proj_w,  2048, 0, 2048, WxpS, 96*2048);
    convert_split_kernel<<<(2048*64+255)/256,   256>>>(dt_proj_w, 64,   0, 64,   WdtS, 2048*64);
    convert_split_kernel<<<(1024*2048+255)/256, 256>>>(out_proj_w,2048, 0, 2048, WoutS,1024*2048);
    rmsnorm_split_kernel<<<NTOK, 256>>>(hidden, norm1_w, uS);

    // 6) in_proj: [2048,1024] x [4096,1024]^T -> xz fp32
    gemm_big<0,false,true><<<dim3(32,8), 512, 3*BSTG_BYTES>>>(
        uS, WinS, 1024, 4096, nullptr, nullptr, 0, xz, 2*DI, nullptr);

    convert_split_kernel<<<(4096*1024+255)/256, 256>>>(fc1_w, 1024, 0, 1024, Wfc1S, 4096*1024);
    convert_split_kernel<<<(1024*4096+255)/256, 256>>>(fc2_w, 4096, 0, 4096, Wfc2S, 1024*4096);

    // conv + silu
    conv_silu_kernel<<<(NTOK*DI+255)/256, 256>>>(xz, conv_w, conv_b, xc, xcS);

    // x_proj split-K=8: [2048,2048] x [96,2048]^T -> partials -> xdbl
    gemm_tc<0,false,true><<<dim3(1,16,8), 256>>>(
        xcS, WxpS, 2048, 256, 96, nullptr, nullptr, 0, part, 96, nullptr);
    reduce_epi<0,true,false><<<(NTOK*96/4+255)/256, 256>>>(
        part, 8, 96, nullptr, nullptr, 0, xdbl, 96, nullptr);

    // split dt_in columns
    convert_split_kernel<<<(NTOK*DTR+255)/256, 256>>>(xdbl, 96, 0, DTR, dtAS, NTOK*DTR);

    // dt_proj + softplus(+bias)
    gemm_tc<3,false,true><<<dim3(16,16), 256>>>(
        dtAS, WdtS, 64, 64, 2048, dt_proj_b, nullptr, 0, dt, DI, nullptr);

    // selective scan + gating
    scan_kernel<<<(BB*DI*4)/128, 128>>>(dt, xc, xdbl, xz, A_log, D_param, ymS);

    // out_proj split-K=2 + residual(hidden) -> h
    gemm_tc<0,false,true><<<dim3(8,16,2), 256>>>(
        ymS, WoutS, 2048, 1024, 1024, nullptr, nullptr, 0, part, 1024, nullptr);
    reduce_epi<4,true,false><<<(NTOK*1024/4+255)/256, 256>>>(
        part, 2, 1024, nullptr, hidden, DD, h, DD, nullptr);

    // rmsnorm2
    rmsnorm_split_kernel<<<NTOK, 256>>>(h, norm2_w, hnS);

    // fc1 + bias + silu -> m1 split
    gemm_big<2,true,false><<<dim3(32,8), 512, 3*BSTG_BYTES>>>(
        hnS, Wfc1S, 1024, 4096, fc1_b, nullptr, 0, nullptr, 0, m1S);

    // fc2 split-K=2 + bias + residual(h) -> out
    gemm_tc<0,false,true><<<dim3(8,16,2), 256>>>(
        m1S, Wfc2S, 4096, 2048, 1024, nullptr, nullptr, 0, part, 1024, nullptr);
    reduce_epi<5,true,false><<<(NTOK*1024/4+255)/256, 256>>>(
        part, 2, 1024, fc2_b, h, DD, out, DD, nullptr);
}

// round 6
// speedup vs baseline: 2.3967x; 1.0437x over previous
#include <cuda_runtime.h>
#include <cuda_bf16.h>
#include <cstdint>
#include <cstddef>

#define BB 2
#define LL 1024
#define DD 1024
#define DI 2048
#define DS 16
#define DC 4
#define DTR 64
#define NTOK (BB*LL)

// ---------------- scratch -------------------------------------------------------
__device__ float g_xz  [NTOK*2*DI];
__device__ float g_xc  [NTOK*DI];
__device__ float g_xdbl[NTOK*96];
__device__ float g_dt  [NTOK*DI];
__device__ float g_h   [NTOK*DD];
__device__ float g_part[8*NTOK*1024];
__device__ __nv_bfloat16 g_uS   [NTOK*2*DD];
__device__ __nv_bfloat16 g_xcS  [NTOK*2*DI];
__device__ __nv_bfloat16 g_dtAS [NTOK*2*DTR];
__device__ __nv_bfloat16 g_ymS  [NTOK*2*DI];
__device__ __nv_bfloat16 g_hnS  [NTOK*2*DD];
__device__ __nv_bfloat16 g_m1S  [NTOK*2*4*DD];
__device__ __nv_bfloat16 g_WinS [4096*2*1024];
__device__ __nv_bfloat16 g_WxpS [96*2*2048];
__device__ __nv_bfloat16 g_WdtS [2048*2*64];
__device__ __nv_bfloat16 g_WoutS[1024*2*2048];
__device__ __nv_bfloat16 g_Wfc1S[4096*2*1024];
__device__ __nv_bfloat16 g_Wfc2S[1024*2*4096];

// ---------------- PTX helpers ----------------------------------------------------
__device__ __forceinline__ uint32_t smem_u32(const void* p){
    uint32_t a;
    asm("{ .reg .u64 t; cvta.to.shared.u64 t, %1; cvt.u32.u64 %0, t; }" : "=r"(a) : "l"(p));
    return a;
}
__device__ __forceinline__ void cp_async16(uint32_t dst, const void* src, uint32_t sz){
    asm volatile("cp.async.cg.shared.global [%0], [%1], 16, %2;"
                 :: "r"(dst), "l"(src), "r"(sz));
}
__device__ __forceinline__ void cp_commit(){
    asm volatile("cp.async.commit_group;" ::: "memory");
}
__device__ __forceinline__ void cp_wait1(){
    asm volatile("cp.async.wait_group 1;" ::: "memory");
}
__device__ __forceinline__ void ldsm_x4(uint32_t* r, uint32_t addr){
    asm volatile("ldmatrix.sync.aligned.m8n8.x4.shared.b16 {%0,%1,%2,%3}, [%4];"
                 : "=r"(r[0]),"=r"(r[1]),"=r"(r[2]),"=r"(r[3]) : "r"(addr));
}
__device__ __forceinline__ void mma_bf16(float* c, const uint32_t* a, const uint32_t* b){
    asm volatile(
        "mma.sync.aligned.m16n8k16.row.col.f32.bf16.bf16.f32 "
        "{%0,%1,%2,%3}, {%4,%5,%6,%7}, {%8,%9}, {%0,%1,%2,%3};"
        : "+f"(c[0]), "+f"(c[1]), "+f"(c[2]), "+f"(c[3])
        : "r"(a[0]), "r"(a[1]), "r"(a[2]), "r"(a[3]), "r"(b[0]), "r"(b[1]));
}
__device__ __forceinline__ uint32_t sw_off(int m, int q){
    return (uint32_t)(((m >> 1) << 7) + (((((m & 1) << 2) | q) ^ ((m >> 1) & 7)) << 4));
}
__device__ __forceinline__ void seg_k(int ks, int stepsPerSeg, int kc, int Ktot,
                                      int& kA, int& kB){
    const int seg = ks / stepsPerSeg;
    const int off = (ks - seg * stepsPerSeg) * 32 + kc;
    kA = (seg == 1) ? (Ktot + off) : off;
    kB = (seg == 2) ? (Ktot + off) : off;
}

// ---------------- persistent mma.sync GEMM, 128x128 tile, split-K capable --------
// EPI: 0 none, 2 silu(+bias), 3 softplus(+bias)
#define STG_BYTES 16384
template<int EPI, bool SPLITOUT, bool FP32OUT>
__global__ void __launch_bounds__(256, 2)
gemm_tc(const __nv_bfloat16* __restrict__ A,
        const __nv_bfloat16* __restrict__ Bm,
        int Ktot, int Ksub, int N,
        const float* __restrict__ bias,
        float* __restrict__ C, int ldc,
        __nv_bfloat16* __restrict__ Cs)
{
    __shared__ __align__(128) char smem_buf[3 * STG_BYTES];
    const uint32_t sb = smem_u32(smem_buf);
    const int t = threadIdx.x;
    const int lane = t & 31;
    const int wid = t >> 5;
    const int warp_m = wid & 1;
    const int warp_n = wid >> 1;
    const int kc = blockIdx.z * Ksub;
    C += (size_t)blockIdx.z * NTOK * ldc;
    const int ldab = 2 * Ktot;
    const int stepsPerSeg = Ksub / 32;
    const int KS = 3 * stepsPerSeg;
    const int ntx = (N + 127) >> 7;
    const int numTiles = ntx * (NTOK >> 7);

    const int mat = lane >> 3;
    const int rin = lane & 7;
    const int a_row_base = warp_m * 64 + ((mat & 1) << 3) + rin;
    const int a_qhi = mat >> 1;
    const int b_row4 = warp_n * 32 + ((mat >> 1) << 3) + rin;  // for ldsm_x4 B
    const int b_q = mat & 1;
    const int erow = lane >> 2;
    const int ecol = (lane & 3) << 1;

    for (int tile = blockIdx.x; tile < numTiles; tile += gridDim.x){
        const int m0 = (tile & ((NTOK >> 7) - 1)) << 7;   // m-fastest
        const int n0 = (tile / (NTOK >> 7)) << 7;

        float acc[4][4][4];
        #pragma unroll
        for (int i = 0; i < 4; i++)
            #pragma unroll
            for (int j = 0; j < 4; j++)
                #pragma unroll
                for (int c = 0; c < 4; c++) acc[i][j][c] = 0.f;

        auto load_stage = [&](int ks){
            int kA, kB; seg_k(ks, stepsPerSeg, kc, Ktot, kA, kB);
            const uint32_t aB = sb + (uint32_t)(ks % 3) * STG_BYTES;
            const uint32_t bB = aB + 8192u;
            const __nv_bfloat16* As = A  + (size_t)m0 * ldab + kA;
            const __nv_bfloat16* Bs = Bm + (size_t)n0 * ldab + kB;
            #pragma unroll
            for (int p = 0; p < 2; p++){
                const int e = (p << 8) + t;
                const int r = e >> 2, q = e & 3;
                cp_async16(aB + sw_off(r, q), (const void*)(As + (size_t)r * ldab + q * 8), 16u);
            }
            #pragma unroll
            for (int p = 0; p < 2; p++){
                const int e = (p << 8) + t;
                const int r = e >> 2, q = e & 3;
                const bool ok = (n0 + r) < N;
                const __nv_bfloat16* src = Bs + (size_t)(ok ? r : 0) * ldab + q * 8;
                cp_async16(bB + sw_off(r, q), (const void*)src, ok ? 16u : 0u);
            }
        };

        __syncthreads();   // protect smem reuse across tiles
        load_stage(0); cp_commit();
        load_stage(1); cp_commit();

        for (int ks = 0; ks < KS; ks++){
            cp_wait1();
            __syncthreads();
            if (ks + 2 < KS) load_stage(ks + 2);
            cp_commit();

            const uint32_t aB = sb + (uint32_t)(ks % 3) * STG_BYTES;
            const uint32_t bB = aB + 8192u;
            #pragma unroll
            for (int k2 = 0; k2 < 2; k2++){
                uint32_t afr[4][4], bfr2[2][4];
                #pragma unroll
                for (int mt = 0; mt < 4; mt++)
                    ldsm_x4(afr[mt], aB + sw_off(a_row_base + mt * 16, k2 * 2 + a_qhi));
                #pragma unroll
                for (int np = 0; np < 2; np++)
                    ldsm_x4(bfr2[np], bB + sw_off(b_row4 + np * 16, k2 * 2 + b_q));
                #pragma unroll
                for (int mt = 0; mt < 4; mt++)
                    #pragma unroll
                    for (int nt = 0; nt < 4; nt++)
                        mma_bf16(acc[mt][nt], afr[mt], &bfr2[nt >> 1][(nt & 1) << 1]);
            }
        }

        #pragma unroll
        for (int mt = 0; mt < 4; mt++){
            #pragma unroll
            for (int nt = 0; nt < 4; nt++){
                const int n = n0 + warp_n * 32 + nt * 8 + ecol;
                if (n >= N) continue;
                #pragma unroll
                for (int half = 0; half < 2; half++){
                    const int m = m0 + warp_m * 64 + mt * 16 + erow + half * 8;
                    float v0 = acc[mt][nt][half * 2 + 0];
                    float v1 = acc[mt][nt][half * 2 + 1];
                    if (EPI == 2 || EPI == 3){ v0 += bias[n]; v1 += bias[n + 1]; }
                    if (EPI == 2){
                        v0 = v0 / (1.f + __expf(-v0)); v1 = v1 / (1.f + __expf(-v1));
                    }
                    if (EPI == 3){
                        v0 = (v0 > 20.f) ? v0 : log1pf(__expf(v0));
                        v1 = (v1 > 20.f) ? v1 : log1pf(__expf(v1));
                    }
                    if (FP32OUT){
                        float2 o; o.x = v0; o.y = v1;
                        *reinterpret_cast<float2*>(&C[(size_t)m * ldc + n]) = o;
                    }
                    if (SPLITOUT){
                        __nv_bfloat16 h0 = __float2bfloat16(v0);
                        __nv_bfloat16 h1 = __float2bfloat16(v1);
                        __nv_bfloat162 hh; hh.x = h0; hh.y = h1;
                        __nv_bfloat162 ll;
                        ll.x = __float2bfloat16(v0 - __bfloat162float(h0));
                        ll.y = __float2bfloat16(v1 - __bfloat162float(h1));
                        *reinterpret_cast<__nv_bfloat162*>(&Cs[(size_t)m * (2*N) + n]) = hh;
                        *reinterpret_cast<__nv_bfloat162*>(&Cs[(size_t)m * (2*N) + N + n]) = ll;
                    }
                }
            }
        }
    }
}

// ---------------- split-K reduce + fused epilogue ---------------------------------
template<int EPI, bool FP32OUT, bool SPLITOUT>
__global__ void reduce_epi(const float* __restrict__ P, int S, int N,
                           const float* __restrict__ bias,
                           const float* __restrict__ R, int ldr,
                           float* __restrict__ C, int ldc,
                           __nv_bfloat16* __restrict__ Cs)
{
    const int i = blockIdx.x * 256 + threadIdx.x;
    const int tot = NTOK * N / 4;
    if (i >= tot) return;
    const int m = (i * 4) / N;
    const int n = (i * 4) - m * N;
    const float4* Pv = reinterpret_cast<const float4*>(P);
    float4 a = Pv[i];
    for (int s = 1; s < S; s++){
        const float4 b = Pv[(size_t)s * tot + i];
        a.x += b.x; a.y += b.y; a.z += b.z; a.w += b.w;
    }
    float v[4] = {a.x, a.y, a.z, a.w};
    if (EPI == 5){
        #pragma unroll
        for (int j = 0; j < 4; j++) v[j] += bias[n + j];
    }
    if (EPI == 4 || EPI == 5){
        const float4 rv = *reinterpret_cast<const float4*>(&R[(size_t)m * ldr + n]);
        v[0] += rv.x; v[1] += rv.y; v[2] += rv.z; v[3] += rv.w;
    }
    if (FP32OUT){
        float4 o; o.x = v[0]; o.y = v[1]; o.z = v[2]; o.w = v[3];
        *reinterpret_cast<float4*>(&C[(size_t)m * ldc + n]) = o;
    }
    if (SPLITOUT){
        #pragma unroll
        for (int j = 0; j < 4; j++){
            __nv_bfloat16 hi = __float2bfloat16(v[j]);
            Cs[(size_t)m * (2*N) + n + j] = hi;
            Cs[(size_t)m * (2*N) + N + n + j] = __float2bfloat16(v[j] - __bfloat162float(hi));
        }
    }
}

// ---------------- rmsnorm -> split bf16 --------------------------------------------
__global__ void rmsnorm_split_kernel(const float* __restrict__ x,
                                     const float* __restrict__ w,
                                     __nv_bfloat16* __restrict__ o)
{
    const int row = blockIdx.x;
    const float* xr = x + (size_t)row * DD;
    float s = 0.f;
    for (int i = threadIdx.x; i < DD; i += 256) { float v = xr[i]; s += v * v; }
    #pragma unroll
    for (int off = 16; off > 0; off >>= 1) s += __shfl_xor_sync(0xffffffffu, s, off);
    __shared__ float red[8];
    int lane = threadIdx.x & 31, warp = threadIdx.x >> 5;
    if (lane == 0) red[warp] = s;
    __syncthreads();
    if (warp == 0) {
        float tt = (lane < 8) ? red[lane] : 0.f;
        #pragma unroll
        for (int off = 4; off > 0; off >>= 1) tt += __shfl_xor_sync(0xffffffffu, tt, off);
        if (lane == 0) red[0] = tt;
    }
    __syncthreads();
    const float scale = rsqrtf(red[0] * (1.0f / DD) + 1e-6f);
    for (int i = threadIdx.x; i < DD; i += 256) {
        float v = w[i] * xr[i] * scale;
        __nv_bfloat16 hi = __float2bfloat16(v);
        o[(size_t)row * 2 * DD + i] = hi;
        o[(size_t)row * 2 * DD + DD + i] = __float2bfloat16(v - __bfloat162float(hi));
    }
}

// ---------------- conv + silu (vectorized x4) ---------------------------------------
__global__ void conv_silu_kernel(const float* __restrict__ xz,
                                 const float* __restrict__ cw,
                                 const float* __restrict__ cb,
                                 float* __restrict__ xc,
                                 __nv_bfloat16* __restrict__ xcS)
{
    const int gid = blockIdx.x * blockDim.x + threadIdx.x;
    if (gid >= NTOK * DI / 4) return;
    const int d4 = (gid % (DI / 4)) * 4;
    const int row = gid / (DI / 4);
    const int l = row % LL;
    const int bbase = row - l;

    float acc[4];
    #pragma unroll
    for (int j = 0; j < 4; j++) acc[j] = cb[d4 + j];
    #pragma unroll
    for (int k = 0; k < DC; k++) {
        const int ll = l + k - (DC - 1);
        if (ll >= 0){
            const float4 xv = *reinterpret_cast<const float4*>(
                &xz[(size_t)(bbase + ll) * (2 * DI) + d4]);
            acc[0] += cw[(d4 + 0) * DC + k] * xv.x;
            acc[1] += cw[(d4 + 1) * DC + k] * xv.y;
            acc[2] += cw[(d4 + 2) * DC + k] * xv.z;
            acc[3] += cw[(d4 + 3) * DC + k] * xv.w;
        }
    }
    float4 so;
    float* sp = reinterpret_cast<float*>(&so);
    __nv_bfloat162 hh[2], ll2[2];
    #pragma unroll
    for (int j = 0; j < 4; j++){
        const float s = acc[j] / (1.f + __expf(-acc[j]));
        sp[j] = s;
        __nv_bfloat16 hi = __float2bfloat16(s);
        if (j & 1){ hh[j >> 1].y = hi; ll2[j >> 1].y = __float2bfloat16(s - __bfloat162float(hi)); }
        else      { hh[j >> 1].x = hi; ll2[j >> 1].x = __float2bfloat16(s - __bfloat162float(hi)); }
    }
    *reinterpret_cast<float4*>(&xc[(size_t)row * DI + d4]) = so;
    *reinterpret_cast<uint2*>(&xcS[(size_t)row * 2 * DI + d4]) = *reinterpret_cast<uint2*>(hh);
    *reinterpret_cast<uint2*>(&xcS[(size_t)row * 2 * DI + DI + d4]) = *reinterpret_cast<uint2*>(ll2);
}

// ---------------- fp32 -> split-bf16 converter (vectorized x8) ----------------------
__global__ void convert_split8(const float* __restrict__ src, int ld,
                               int K, __nv_bfloat16* __restrict__ dst, int total8)
{
    const int i = blockIdx.x * 256 + threadIdx.x;
    if (i >= total8) return;
    const int K8 = K >> 3;
    const int r = i / K8, c = (i - r * K8) << 3;
    const float4 v0 = *reinterpret_cast<const float4*>(&src[(size_t)r * ld + c]);
    const float4 v1 = *reinterpret_cast<const float4*>(&src[(size_t)r * ld + c + 4]);
    const float vv[8] = {v0.x, v0.y, v0.z, v0.w, v1.x, v1.y, v1.z, v1.w};
    __nv_bfloat16 hi[8], lo[8];
    #pragma unroll
    for (int j = 0; j < 8; j++){
        hi[j] = __float2bfloat16(vv[j]);
        lo[j] = __float2bfloat16(vv[j] - __bfloat162float(hi[j]));
    }
    *reinterpret_cast<uint4*>(&dst[(size_t)r * 2 * K + c]) = *reinterpret_cast<uint4*>(hi);
    *reinterpret_cast<uint4*>(&dst[(size_t)r * 2 * K + K + c]) = *reinterpret_cast<uint4*>(lo);
}

// ---------------- selective scan (software pipelined) --------------------------------
__global__ void scan_kernel(const float* __restrict__ dt,
                            const float* __restrict__ xc,
                            const float* __restrict__ xdbl,
                            const float* __restrict__ xz,
                            const float* __restrict__ A_log,
                            const float* __restrict__ Dp,
                            __nv_bfloat16* __restrict__ ymS)
{
    const int gtid = blockIdx.x * blockDim.x + threadIdx.x;
    if (gtid >= BB * DI * 4) return;
    const int sub  = gtid & 3;
    const int pair = gtid >> 2;
    const int d = pair & (DI - 1);
    const int b = pair >> 11;

    float Aj[4];
    #pragma unroll
    for (int j = 0; j < 4; j++)
        Aj[j] = -expf(A_log[d * DS + sub * 4 + j]);
    float h[4] = {0.f, 0.f, 0.f, 0.f};
    const float Dv = Dp[d];

    const float* dtp = dt + (size_t)(b * LL) * DI + d;
    const float* xcp = xc + (size_t)(b * LL) * DI + d;
    const float* xdp = xdbl + (size_t)(b * LL) * 96 + DTR + sub * 4;
    const float* zp  = xz + (size_t)(b * LL) * (2 * DI) + DI + d;
    __nv_bfloat16* yo = ymS + (size_t)(b * LL) * 2 * DI + d;

    float dtv = dtp[0];
    float xv  = xcp[0];
    float4 Bv = *reinterpret_cast<const float4*>(xdp);
    float4 Cv = *reinterpret_cast<const float4*>(xdp + DS);
    float zv  = (sub == 0) ? zp[0] : 0.f;
    float dA[4];
    #pragma unroll
    for (int j = 0; j < 4; j++) dA[j] = __expf(dtv * Aj[j]);

    for (int l = 0; l < LL; l++) {
        float dtn = 0.f, xn = 0.f, zn = 0.f;
        float4 Bn = make_float4(0.f,0.f,0.f,0.f), Cn = Bn;
        if (l + 1 < LL){
            dtn = dtp[(l + 1) * DI];
            xn  = xcp[(l + 1) * DI];
            Bn  = *reinterpret_cast<const float4*>(xdp + (l + 1) * 96);
            Cn  = *reinterpret_cast<const float4*>(xdp + (l + 1) * 96 + DS);
            if (sub == 0) zn = zp[(l + 1) * 2 * DI];
        }
        float dAn[4];
        #pragma unroll
        for (int j = 0; j < 4; j++) dAn[j] = __expf(dtn * Aj[j]);

        const float dx = dtv * xv;
        const float Bt[4] = {Bv.x, Bv.y, Bv.z, Bv.w};
        const float Ct[4] = {Cv.x, Cv.y, Cv.z, Cv.w};
        float y = 0.f;
        #pragma unroll
        for (int j = 0; j < 4; j++) {
            h[j] = dA[j] * h[j] + dx * Bt[j];
            y += h[j] * Ct[j];
        }
        y += __shfl_xor_sync(0xffffffffu, y, 1);
        y += __shfl_xor_sync(0xffffffffu, y, 2);
        if (sub == 0) {
            const float sz = zv / (1.f + __expf(-zv));
            const float val = (y + Dv * xv) * sz;
            __nv_bfloat16 hi = __float2bfloat16(val);
            yo[(size_t)l * 2 * DI] = hi;
            yo[(size_t)l * 2 * DI + DI] = __float2bfloat16(val - __bfloat162float(hi));
        }
        dtv = dtn; xv = xn; zv = zn; Bv = Bn; Cv = Cn;
        #pragma unroll
        for (int j = 0; j < 4; j++) dA[j] = dAn[j];
    }
}

// ---------------- launch --------------------------------------------------------------
extern "C" void kernel_launch(void* const* d_in, const int* in_sizes, int n_in,
                              void* d_out, int out_size)
{
    const float* hidden    = (const float*)d_in[0];
    const float* norm1_w   = (const float*)d_in[1];
    const float* in_proj_w = (const float*)d_in[2];
    const float* conv_w    = (const float*)d_in[3];
    const float* conv_b    = (const float*)d_in[4];
    const float* x_proj_w  = (const float*)d_in[5];
    const float* dt_proj_w = (const float*)d_in[6];
    const float* dt_proj_b = (const float*)d_in[7];
    const float* A_log     = (const float*)d_in[8];
    const float* D_param   = (const float*)d_in[9];
    const float* out_proj_w= (const float*)d_in[10];
    const float* norm2_w   = (const float*)d_in[11];
    const float* fc1_w     = (const float*)d_in[12];
    const float* fc1_b     = (const float*)d_in[13];
    const float* fc2_w     = (const float*)d_in[14];
    const float* fc2_b     = (const float*)d_in[15];
    float* out = (float*)d_out;

    float *xz, *xc, *xdbl, *dt, *h, *part;
    __nv_bfloat16 *uS, *xcS, *dtAS, *ymS, *hnS, *m1S;
    __nv_bfloat16 *WinS, *WxpS, *WdtS, *WoutS, *Wfc1S, *Wfc2S;
    cudaGetSymbolAddress((void**)&xz,   g_xz);
    cudaGetSymbolAddress((void**)&xc,   g_xc);
    cudaGetSymbolAddress((void**)&xdbl, g_xdbl);
    cudaGetSymbolAddress((void**)&dt,   g_dt);
    cudaGetSymbolAddress((void**)&h,    g_h);
    cudaGetSymbolAddress((void**)&part, g_part);
    cudaGetSymbolAddress((void**)&uS,   g_uS);
    cudaGetSymbolAddress((void**)&xcS,  g_xcS);
    cudaGetSymbolAddress((void**)&dtAS, g_dtAS);
    cudaGetSymbolAddress((void**)&ymS,  g_ymS);
    cudaGetSymbolAddress((void**)&hnS,  g_hnS);
    cudaGetSymbolAddress((void**)&m1S,  g_m1S);
    cudaGetSymbolAddress((void**)&WinS, g_WinS);
    cudaGetSymbolAddress((void**)&WxpS, g_WxpS);
    cudaGetSymbolAddress((void**)&WdtS, g_WdtS);
    cudaGetSymbolAddress((void**)&WoutS,g_WoutS);
    cudaGetSymbolAddress((void**)&Wfc1S,g_Wfc1S);
    cudaGetSymbolAddress((void**)&Wfc2S,g_Wfc2S);

    // weight converts (vectorized)
    convert_split8<<<(4096*1024/8+255)/256, 256>>>(in_proj_w, 1024, 1024, WinS, 4096*1024/8);
    convert_split8<<<(96*2048/8+255)/256,   256>>>(x_proj_w,  2048, 2048, WxpS, 96*2048/8);
    convert_split8<<<(2048*64/8+255)/256,   256>>>(dt_proj_w, 64,   64,   WdtS, 2048*64/8);
    convert_split8<<<(1024*2048/8+255)/256, 256>>>(out_proj_w,2048, 2048, WoutS,1024*2048/8);
    rmsnorm_split_kernel<<<NTOK, 256>>>(hidden, norm1_w, uS);

    // in_proj: [2048,1024] x [4096,1024]^T -> xz fp32 (persistent grid)
    gemm_tc<0,false,true><<<dim3(296,1,1), 256>>>(
        uS, WinS, 1024, 1024, 4096, nullptr, xz, 2*DI, nullptr);

    convert_split8<<<(4096*1024/8+255)/256, 256>>>(fc1_w, 1024, 1024, Wfc1S, 4096*1024/8);
    convert_split8<<<(1024*4096/8+255)/256, 256>>>(fc2_w, 4096, 4096, Wfc2S, 1024*4096/8);

    // conv + silu
    conv_silu_kernel<<<(NTOK*DI/4+255)/256, 256>>>(xz, conv_w, conv_b, xc, xcS);

    // x_proj split-K=8 -> partials -> xdbl
    gemm_tc<0,false,true><<<dim3(16,1,8), 256>>>(
        xcS, WxpS, 2048, 256, 96, nullptr, part, 96, nullptr);
    reduce_epi<0,true,false><<<(NTOK*96/4+255)/256, 256>>>(
        part, 8, 96, nullptr, nullptr, 0, xdbl, 96, nullptr);

    // split dt_in columns
    convert_split8<<<(NTOK*DTR/8+255)/256, 256>>>(xdbl, 96, DTR, dtAS, NTOK*DTR/8);

    // dt_proj + softplus(+bias)
    gemm_tc<3,false,true><<<dim3(256,1,1), 256>>>(
        dtAS, WdtS, 64, 64, 2048, dt_proj_b, dt, DI, nullptr);

    // selective scan + gating
    scan_kernel<<<(BB*DI*4)/128, 128>>>(dt, xc, xdbl, xz, A_log, D_param, ymS);

    // out_proj split-K=2 + residual(hidden) -> h
    gemm_tc<0,false,true><<<dim3(128,1,2), 256>>>(
        ymS, WoutS, 2048, 1024, 1024, nullptr, part, 1024, nullptr);
    reduce_epi<4,true,false><<<(NTOK*1024/4+255)/256, 256>>>(
        part, 2, 1024, nullptr, hidden, DD, h, DD, nullptr);

    // rmsnorm2
    rmsnorm_split_kernel<<<NTOK, 256>>>(h, norm2_w, hnS);

    // fc1 + bias + silu -> m1 split (persistent grid)
    gemm_tc<2,true,false><<<dim3(296,1,1), 256>>>(
        hnS, Wfc1S, 1024, 1024, 4096, fc1_b, nullptr, 0, m1S);

    // fc2 split-K=2 + bias + residual(h) -> out
    gemm_tc<0,false,true><<<dim3(128,1,2), 256>>>(
        m1S, Wfc2S, 4096, 2048, 1024, nullptr, part, 1024, nullptr);
    reduce_epi<5,true,false><<<(NTOK*1024/4+255)/256, 256>>>(
        part, 2, 1024, fc2_b, h, DD, out, DD, nullptr);
}

// round 7
// speedup vs baseline: 2.6403x; 1.1016x over previous
#include <cuda_runtime.h>
#include <cuda_bf16.h>
#include <cstdint>
#include <cstddef>

#define BB 2
#define LL 1024
#define DD 1024
#define DI 2048
#define DS 16
#define DC 4
#define DTR 64
#define NTOK (BB*LL)

// ---------------- scratch -------------------------------------------------------
__device__ float g_xz  [NTOK*2*DI];
__device__ float g_xc  [NTOK*DI];
__device__ float g_xdbl[NTOK*96];
__device__ float g_dt  [NTOK*DI];
__device__ float g_h   [NTOK*DD];
__device__ float g_part[8*NTOK*1024];
__device__ __nv_bfloat16 g_uS   [NTOK*2*DD];
__device__ __nv_bfloat16 g_xcS  [NTOK*2*DI];
__device__ __nv_bfloat16 g_dtAS [NTOK*2*DTR];
__device__ __nv_bfloat16 g_ymS  [NTOK*2*DI];
__device__ __nv_bfloat16 g_hnS  [NTOK*2*DD];
__device__ __nv_bfloat16 g_m1S  [NTOK*2*4*DD];
__device__ __nv_bfloat16 g_WinS [4096*2*1024];
__device__ __nv_bfloat16 g_WxpS [96*2*2048];
__device__ __nv_bfloat16 g_WdtS [2048*2*64];
__device__ __nv_bfloat16 g_WoutS[1024*2*2048];
__device__ __nv_bfloat16 g_Wfc1S[4096*2*1024];
__device__ __nv_bfloat16 g_Wfc2S[1024*2*4096];

// ---------------- PTX helpers ----------------------------------------------------
__device__ __forceinline__ uint32_t smem_u32(const void* p){
    uint32_t a;
    asm("{ .reg .u64 t; cvta.to.shared.u64 t, %1; cvt.u32.u64 %0, t; }" : "=r"(a) : "l"(p));
    return a;
}
__device__ __forceinline__ void cp_async16(uint32_t dst, const void* src, uint32_t sz){
    asm volatile("cp.async.cg.shared.global [%0], [%1], 16, %2;"
                 :: "r"(dst), "l"(src), "r"(sz));
}
__device__ __forceinline__ void cp_commit(){
    asm volatile("cp.async.commit_group;" ::: "memory");
}
__device__ __forceinline__ void cp_wait1(){
    asm volatile("cp.async.wait_group 1;" ::: "memory");
}
__device__ __forceinline__ void ldsm_x4(uint32_t* r, uint32_t addr){
    asm volatile("ldmatrix.sync.aligned.m8n8.x4.shared.b16 {%0,%1,%2,%3}, [%4];"
                 : "=r"(r[0]),"=r"(r[1]),"=r"(r[2]),"=r"(r[3]) : "r"(addr));
}
__device__ __forceinline__ void mma_bf16(float* c, const uint32_t* a, const uint32_t* b){
    asm volatile(
        "mma.sync.aligned.m16n8k16.row.col.f32.bf16.bf16.f32 "
        "{%0,%1,%2,%3}, {%4,%5,%6,%7}, {%8,%9}, {%0,%1,%2,%3};"
        : "+f"(c[0]), "+f"(c[1]), "+f"(c[2]), "+f"(c[3])
        : "r"(a[0]), "r"(a[1]), "r"(a[2]), "r"(a[3]), "r"(b[0]), "r"(b[1]));
}
__device__ __forceinline__ uint32_t sw_off(int m, int q){
    return (uint32_t)(((m >> 1) << 7) + (((((m & 1) << 2) | q) ^ ((m >> 1) & 7)) << 4));
}

// ---------------- persistent fused 3-term GEMM, 128x128 tile ----------------------
// Per 32-wide k-chunk: load Ahi/Alo/Bhi/Blo once, run hihi + lohi + hilo mma passes.
// EPI: 0 none, 2 silu(+bias), 3 softplus(+bias)
#define STG_BYTES 32768
template<int EPI, bool SPLITOUT, bool FP32OUT>
__global__ void __launch_bounds__(256, 2)
gemm_tc(const __nv_bfloat16* __restrict__ A,
        const __nv_bfloat16* __restrict__ Bm,
        int Ktot, int Ksub, int N,
        const float* __restrict__ bias,
        float* __restrict__ C, int ldc,
        __nv_bfloat16* __restrict__ Cs)
{
    extern __shared__ __align__(128) char smem_buf[];
    const uint32_t sb = smem_u32(smem_buf);
    const int t = threadIdx.x;
    const int lane = t & 31;
    const int wid = t >> 5;
    const int warp_m = wid & 1;
    const int warp_n = wid >> 1;
    const int kc = blockIdx.z * Ksub;
    C += (size_t)blockIdx.z * NTOK * ldc;
    const int ldab = 2 * Ktot;
    const int KS = Ksub / 32;
    const int ntx = (N + 127) >> 7;
    const int numTiles = ntx * (NTOK >> 7);

    const int mat = lane >> 3;
    const int rin = lane & 7;
    const int a_row_base = warp_m * 64 + ((mat & 1) << 3) + rin;
    const int a_qhi = mat >> 1;
    const int b_row4 = warp_n * 32 + ((mat >> 1) << 3) + rin;
    const int b_q = mat & 1;
    const int erow = lane >> 2;
    const int ecol = (lane & 3) << 1;

    for (int tile = blockIdx.x; tile < numTiles; tile += gridDim.x){
        const int m0 = (tile & ((NTOK >> 7) - 1)) << 7;
        const int n0 = (tile / (NTOK >> 7)) << 7;

        float acc[4][4][4];
        #pragma unroll
        for (int i = 0; i < 4; i++)
            #pragma unroll
            for (int j = 0; j < 4; j++)
                #pragma unroll
                for (int c = 0; c < 4; c++) acc[i][j][c] = 0.f;

        auto load_stage = [&](int ks){
            const int off = kc + ks * 32;
            const uint32_t s0 = sb + (uint32_t)(ks % 3) * STG_BYTES;
            const __nv_bfloat16* Ah = A  + (size_t)m0 * ldab + off;
            const __nv_bfloat16* Bh = Bm + (size_t)n0 * ldab + off;
            #pragma unroll
            for (int p = 0; p < 2; p++){                        // A hi
                const int e = (p << 8) + t;
                const int r = e >> 2, q = e & 3;
                cp_async16(s0 + sw_off(r, q), (const void*)(Ah + (size_t)r * ldab + q * 8), 16u);
            }
            #pragma unroll
            for (int p = 0; p < 2; p++){                        // A lo
                const int e = (p << 8) + t;
                const int r = e >> 2, q = e & 3;
                cp_async16(s0 + 8192u + sw_off(r, q),
                           (const void*)(Ah + Ktot + (size_t)r * ldab + q * 8), 16u);
            }
            #pragma unroll
            for (int p = 0; p < 2; p++){                        // B hi
                const int e = (p << 8) + t;
                const int r = e >> 2, q = e & 3;
                const bool ok = (n0 + r) < N;
                const __nv_bfloat16* src = Bh + (size_t)(ok ? r : 0) * ldab + q * 8;
                cp_async16(s0 + 16384u + sw_off(r, q), (const void*)src, ok ? 16u : 0u);
            }
            #pragma unroll
            for (int p = 0; p < 2; p++){                        // B lo
                const int e = (p << 8) + t;
                const int r = e >> 2, q = e & 3;
                const bool ok = (n0 + r) < N;
                const __nv_bfloat16* src = Bh + Ktot + (size_t)(ok ? r : 0) * ldab + q * 8;
                cp_async16(s0 + 24576u + sw_off(r, q), (const void*)src, ok ? 16u : 0u);
            }
        };

        __syncthreads();
        load_stage(0); cp_commit();
        load_stage(1); cp_commit();

        for (int ks = 0; ks < KS; ks++){
            cp_wait1();
            __syncthreads();
            if (ks + 2 < KS) load_stage(ks + 2);
            cp_commit();

            const uint32_t aB = sb + (uint32_t)(ks % 3) * STG_BYTES;
            #pragma unroll
            for (int k2 = 0; k2 < 2; k2++){
                uint32_t ah[4][4], bh[2][4];
                #pragma unroll
                for (int mt = 0; mt < 4; mt++)
                    ldsm_x4(ah[mt], aB + sw_off(a_row_base + mt * 16, k2 * 2 + a_qhi));
                #pragma unroll
                for (int np = 0; np < 2; np++)
                    ldsm_x4(bh[np], aB + 16384u + sw_off(b_row4 + np * 16, k2 * 2 + b_q));
                #pragma unroll
                for (int mt = 0; mt < 4; mt++)
                    #pragma unroll
                    for (int nt = 0; nt < 4; nt++)
                        mma_bf16(acc[mt][nt], ah[mt], &bh[nt >> 1][(nt & 1) << 1]);

                uint32_t al[4][4];
                #pragma unroll
                for (int mt = 0; mt < 4; mt++)
                    ldsm_x4(al[mt], aB + 8192u + sw_off(a_row_base + mt * 16, k2 * 2 + a_qhi));
                #pragma unroll
                for (int mt = 0; mt < 4; mt++)
                    #pragma unroll
                    for (int nt = 0; nt < 4; nt++)
                        mma_bf16(acc[mt][nt], al[mt], &bh[nt >> 1][(nt & 1) << 1]);

                uint32_t bl[2][4];
                #pragma unroll
                for (int np = 0; np < 2; np++)
                    ldsm_x4(bl[np], aB + 24576u + sw_off(b_row4 + np * 16, k2 * 2 + b_q));
                #pragma unroll
                for (int mt = 0; mt < 4; mt++)
                    #pragma unroll
                    for (int nt = 0; nt < 4; nt++)
                        mma_bf16(acc[mt][nt], ah[mt], &bl[nt >> 1][(nt & 1) << 1]);
            }
        }

        #pragma unroll
        for (int mt = 0; mt < 4; mt++){
            #pragma unroll
            for (int nt = 0; nt < 4; nt++){
                const int n = n0 + warp_n * 32 + nt * 8 + ecol;
                if (n >= N) continue;
                #pragma unroll
                for (int half = 0; half < 2; half++){
                    const int m = m0 + warp_m * 64 + mt * 16 + erow + half * 8;
                    float v0 = acc[mt][nt][half * 2 + 0];
                    float v1 = acc[mt][nt][half * 2 + 1];
                    if (EPI == 2 || EPI == 3){ v0 += bias[n]; v1 += bias[n + 1]; }
                    if (EPI == 2){
                        v0 = v0 / (1.f + __expf(-v0)); v1 = v1 / (1.f + __expf(-v1));
                    }
                    if (EPI == 3){
                        v0 = (v0 > 20.f) ? v0 : log1pf(__expf(v0));
                        v1 = (v1 > 20.f) ? v1 : log1pf(__expf(v1));
                    }
                    if (FP32OUT){
                        float2 o; o.x = v0; o.y = v1;
                        *reinterpret_cast<float2*>(&C[(size_t)m * ldc + n]) = o;
                    }
                    if (SPLITOUT){
                        __nv_bfloat16 h0 = __float2bfloat16(v0);
                        __nv_bfloat16 h1 = __float2bfloat16(v1);
                        __nv_bfloat162 hh; hh.x = h0; hh.y = h1;
                        __nv_bfloat162 ll;
                        ll.x = __float2bfloat16(v0 - __bfloat162float(h0));
                        ll.y = __float2bfloat16(v1 - __bfloat162float(h1));
                        *reinterpret_cast<__nv_bfloat162*>(&Cs[(size_t)m * (2*N) + n]) = hh;
                        *reinterpret_cast<__nv_bfloat162*>(&Cs[(size_t)m * (2*N) + N + n]) = ll;
                    }
                }
            }
        }
    }
}

// ---------------- split-K reduce + fused epilogue ---------------------------------
template<int EPI, bool FP32OUT, bool SPLITOUT>
__global__ void reduce_epi(const float* __restrict__ P, int S, int N,
                           const float* __restrict__ bias,
                           const float* __restrict__ R, int ldr,
                           float* __restrict__ C, int ldc,
                           __nv_bfloat16* __restrict__ Cs)
{
    const int i = blockIdx.x * 256 + threadIdx.x;
    const int tot = NTOK * N / 4;
    if (i >= tot) return;
    const int m = (i * 4) / N;
    const int n = (i * 4) - m * N;
    const float4* Pv = reinterpret_cast<const float4*>(P);
    float4 a = Pv[i];
    for (int s = 1; s < S; s++){
        const float4 b = Pv[(size_t)s * tot + i];
        a.x += b.x; a.y += b.y; a.z += b.z; a.w += b.w;
    }
    float v[4] = {a.x, a.y, a.z, a.w};
    if (EPI == 5){
        #pragma unroll
        for (int j = 0; j < 4; j++) v[j] += bias[n + j];
    }
    if (EPI == 4 || EPI == 5){
        const float4 rv = *reinterpret_cast<const float4*>(&R[(size_t)m * ldr + n]);
        v[0] += rv.x; v[1] += rv.y; v[2] += rv.z; v[3] += rv.w;
    }
    if (FP32OUT){
        float4 o; o.x = v[0]; o.y = v[1]; o.z = v[2]; o.w = v[3];
        *reinterpret_cast<float4*>(&C[(size_t)m * ldc + n]) = o;
    }
    if (SPLITOUT){
        #pragma unroll
        for (int j = 0; j < 4; j++){
            __nv_bfloat16 hi = __float2bfloat16(v[j]);
            Cs[(size_t)m * (2*N) + n + j] = hi;
            Cs[(size_t)m * (2*N) + N + n + j] = __float2bfloat16(v[j] - __bfloat162float(hi));
        }
    }
}

// ---------------- rmsnorm -> split bf16 (float4) -----------------------------------
__global__ void rmsnorm_split_kernel(const float* __restrict__ x,
                                     const float* __restrict__ w,
                                     __nv_bfloat16* __restrict__ o)
{
    const int row = blockIdx.x;
    const float* xr = x + (size_t)row * DD;
    const int i4 = threadIdx.x * 4;
    const float4 xv = *reinterpret_cast<const float4*>(&xr[i4]);
    float s = xv.x*xv.x + xv.y*xv.y + xv.z*xv.z + xv.w*xv.w;
    #pragma unroll
    for (int off = 16; off > 0; off >>= 1) s += __shfl_xor_sync(0xffffffffu, s, off);
    __shared__ float red[8];
    int lane = threadIdx.x & 31, warp = threadIdx.x >> 5;
    if (lane == 0) red[warp] = s;
    __syncthreads();
    if (warp == 0) {
        float tt = (lane < 8) ? red[lane] : 0.f;
        #pragma unroll
        for (int off = 4; off > 0; off >>= 1) tt += __shfl_xor_sync(0xffffffffu, tt, off);
        if (lane == 0) red[0] = tt;
    }
    __syncthreads();
    const float scale = rsqrtf(red[0] * (1.0f / DD) + 1e-6f);
    const float4 wv = *reinterpret_cast<const float4*>(&w[i4]);
    float v[4] = {wv.x*xv.x*scale, wv.y*xv.y*scale, wv.z*xv.z*scale, wv.w*xv.w*scale};
    __nv_bfloat16 hi[4], lo[4];
    #pragma unroll
    for (int j = 0; j < 4; j++){
        hi[j] = __float2bfloat16(v[j]);
        lo[j] = __float2bfloat16(v[j] - __bfloat162float(hi[j]));
    }
    *reinterpret_cast<uint2*>(&o[(size_t)row * 2 * DD + i4]) = *reinterpret_cast<uint2*>(hi);
    *reinterpret_cast<uint2*>(&o[(size_t)row * 2 * DD + DD + i4]) = *reinterpret_cast<uint2*>(lo);
}

// ---------------- conv + silu (vectorized x4) ---------------------------------------
__global__ void conv_silu_kernel(const float* __restrict__ xz,
                                 const float* __restrict__ cw,
                                 const float* __restrict__ cb,
                                 float* __restrict__ xc,
                                 __nv_bfloat16* __restrict__ xcS)
{
    const int gid = blockIdx.x * blockDim.x + threadIdx.x;
    if (gid >= NTOK * DI / 4) return;
    const int d4 = (gid % (DI / 4)) * 4;
    const int row = gid / (DI / 4);
    const int l = row % LL;
    const int bbase = row - l;

    float acc[4];
    #pragma unroll
    for (int j = 0; j < 4; j++) acc[j] = cb[d4 + j];
    #pragma unroll
    for (int k = 0; k < DC; k++) {
        const int ll = l + k - (DC - 1);
        if (ll >= 0){
            const float4 xv = *reinterpret_cast<const float4*>(
                &xz[(size_t)(bbase + ll) * (2 * DI) + d4]);
            acc[0] += cw[(d4 + 0) * DC + k] * xv.x;
            acc[1] += cw[(d4 + 1) * DC + k] * xv.y;
            acc[2] += cw[(d4 + 2) * DC + k] * xv.z;
            acc[3] += cw[(d4 + 3) * DC + k] * xv.w;
        }
    }
    float4 so;
    float* sp = reinterpret_cast<float*>(&so);
    __nv_bfloat16 hh[4], ll2[4];
    #pragma unroll
    for (int j = 0; j < 4; j++){
        const float s = acc[j] / (1.f + __expf(-acc[j]));
        sp[j] = s;
        hh[j] = __float2bfloat16(s);
        ll2[j] = __float2bfloat16(s - __bfloat162float(hh[j]));
    }
    *reinterpret_cast<float4*>(&xc[(size_t)row * DI + d4]) = so;
    *reinterpret_cast<uint2*>(&xcS[(size_t)row * 2 * DI + d4]) = *reinterpret_cast<uint2*>(hh);
    *reinterpret_cast<uint2*>(&xcS[(size_t)row * 2 * DI + DI + d4]) = *reinterpret_cast<uint2*>(ll2);
}

// ---------------- fp32 -> split-bf16 converter (vectorized x8) ----------------------
__global__ void convert_split8(const float* __restrict__ src, int ld,
                               int K, __nv_bfloat16* __restrict__ dst, int total8)
{
    const int i = blockIdx.x * 256 + threadIdx.x;
    if (i >= total8) return;
    const int K8 = K >> 3;
    const int r = i / K8, c = (i - r * K8) << 3;
    const float4 v0 = *reinterpret_cast<const float4*>(&src[(size_t)r * ld + c]);
    const float4 v1 = *reinterpret_cast<const float4*>(&src[(size_t)r * ld + c + 4]);
    const float vv[8] = {v0.x, v0.y, v0.z, v0.w, v1.x, v1.y, v1.z, v1.w};
    __nv_bfloat16 hi[8], lo[8];
    #pragma unroll
    for (int j = 0; j < 8; j++){
        hi[j] = __float2bfloat16(vv[j]);
        lo[j] = __float2bfloat16(vv[j] - __bfloat162float(hi[j]));
    }
    *reinterpret_cast<uint4*>(&dst[(size_t)r * 2 * K + c]) = *reinterpret_cast<uint4*>(hi);
    *reinterpret_cast<uint4*>(&dst[(size_t)r * 2 * K + K + c]) = *reinterpret_cast<uint4*>(lo);
}

// ---------------- selective scan (software pipelined) --------------------------------
__global__ void scan_kernel(const float* __restrict__ dt,
                            const float* __restrict__ xc,
                            const float* __restrict__ xdbl,
                            const float* __restrict__ xz,
                            const float* __restrict__ A_log,
                            const float* __restrict__ Dp,
                            __nv_bfloat16* __restrict__ ymS)
{
    const int gtid = blockIdx.x * blockDim.x + threadIdx.x;
    if (gtid >= BB * DI * 4) return;
    const int sub  = gtid & 3;
    const int pair = gtid >> 2;
    const int d = pair & (DI - 1);
    const int b = pair >> 11;

    float Aj[4];
    #pragma unroll
    for (int j = 0; j < 4; j++)
        Aj[j] = -expf(A_log[d * DS + sub * 4 + j]);
    float h[4] = {0.f, 0.f, 0.f, 0.f};
    const float Dv = Dp[d];

    const float* dtp = dt + (size_t)(b * LL) * DI + d;
    const float* xcp = xc + (size_t)(b * LL) * DI + d;
    const float* xdp = xdbl + (size_t)(b * LL) * 96 + DTR + sub * 4;
    const float* zp  = xz + (size_t)(b * LL) * (2 * DI) + DI + d;
    __nv_bfloat16* yo = ymS + (size_t)(b * LL) * 2 * DI + d;

    float dtv = dtp[0];
    float xv  = xcp[0];
    float4 Bv = *reinterpret_cast<const float4*>(xdp);
    float4 Cv = *reinterpret_cast<const float4*>(xdp + DS);
    float zv  = (sub == 0) ? zp[0] : 0.f;
    float dA[4];
    #pragma unroll
    for (int j = 0; j < 4; j++) dA[j] = __expf(dtv * Aj[j]);

    for (int l = 0; l < LL; l++) {
        float dtn = 0.f, xn = 0.f, zn = 0.f;
        float4 Bn = make_float4(0.f,0.f,0.f,0.f), Cn = Bn;
        if (l + 1 < LL){
            dtn = dtp[(l + 1) * DI];
            xn  = xcp[(l + 1) * DI];
            Bn  = *reinterpret_cast<const float4*>(xdp + (l + 1) * 96);
            Cn  = *reinterpret_cast<const float4*>(xdp + (l + 1) * 96 + DS);
            if (sub == 0) zn = zp[(l + 1) * 2 * DI];
        }
        float dAn[4];
        #pragma unroll
        for (int j = 0; j < 4; j++) dAn[j] = __expf(dtn * Aj[j]);

        const float dx = dtv * xv;
        const float Bt[4] = {Bv.x, Bv.y, Bv.z, Bv.w};
        const float Ct[4] = {Cv.x, Cv.y, Cv.z, Cv.w};
        float y = 0.f;
        #pragma unroll
        for (int j = 0; j < 4; j++) {
            h[j] = dA[j] * h[j] + dx * Bt[j];
            y += h[j] * Ct[j];
        }
        y += __shfl_xor_sync(0xffffffffu, y, 1);
        y += __shfl_xor_sync(0xffffffffu, y, 2);
        if (sub == 0) {
            const float sz = zv / (1.f + __expf(-zv));
            const float val = (y + Dv * xv) * sz;
            __nv_bfloat16 hi = __float2bfloat16(val);
            yo[(size_t)l * 2 * DI] = hi;
            yo[(size_t)l * 2 * DI + DI] = __float2bfloat16(val - __bfloat162float(hi));
        }
        dtv = dtn; xv = xn; zv = zn; Bv = Bn; Cv = Cn;
        #pragma unroll
        for (int j = 0; j < 4; j++) dA[j] = dAn[j];
    }
}

// ---------------- launch --------------------------------------------------------------
extern "C" void kernel_launch(void* const* d_in, const int* in_sizes, int n_in,
                              void* d_out, int out_size)
{
    const float* hidden    = (const float*)d_in[0];
    const float* norm1_w   = (const float*)d_in[1];
    const float* in_proj_w = (const float*)d_in[2];
    const float* conv_w    = (const float*)d_in[3];
    const float* conv_b    = (const float*)d_in[4];
    const float* x_proj_w  = (const float*)d_in[5];
    const float* dt_proj_w = (const float*)d_in[6];
    const float* dt_proj_b = (const float*)d_in[7];
    const float* A_log     = (const float*)d_in[8];
    const float* D_param   = (const float*)d_in[9];
    const float* out_proj_w= (const float*)d_in[10];
    const float* norm2_w   = (const float*)d_in[11];
    const float* fc1_w     = (const float*)d_in[12];
    const float* fc1_b     = (const float*)d_in[13];
    const float* fc2_w     = (const float*)d_in[14];
    const float* fc2_b     = (const float*)d_in[15];
    float* out = (float*)d_out;

    float *xz, *xc, *xdbl, *dt, *h, *part;
    __nv_bfloat16 *uS, *xcS, *dtAS, *ymS, *hnS, *m1S;
    __nv_bfloat16 *WinS, *WxpS, *WdtS, *WoutS, *Wfc1S, *Wfc2S;
    cudaGetSymbolAddress((void**)&xz,   g_xz);
    cudaGetSymbolAddress((void**)&xc,   g_xc);
    cudaGetSymbolAddress((void**)&xdbl, g_xdbl);
    cudaGetSymbolAddress((void**)&dt,   g_dt);
    cudaGetSymbolAddress((void**)&h,    g_h);
    cudaGetSymbolAddress((void**)&part, g_part);
    cudaGetSymbolAddress((void**)&uS,   g_uS);
    cudaGetSymbolAddress((void**)&xcS,  g_xcS);
    cudaGetSymbolAddress((void**)&dtAS, g_dtAS);
    cudaGetSymbolAddress((void**)&ymS,  g_ymS);
    cudaGetSymbolAddress((void**)&hnS,  g_hnS);
    cudaGetSymbolAddress((void**)&m1S,  g_m1S);
    cudaGetSymbolAddress((void**)&WinS, g_WinS);
    cudaGetSymbolAddress((void**)&WxpS, g_WxpS);
    cudaGetSymbolAddress((void**)&WdtS, g_WdtS);
    cudaGetSymbolAddress((void**)&WoutS,g_WoutS);
    cudaGetSymbolAddress((void**)&Wfc1S,g_Wfc1S);
    cudaGetSymbolAddress((void**)&Wfc2S,g_Wfc2S);

    const int SM = 3 * STG_BYTES;
    cudaFuncSetAttribute(gemm_tc<0,false,true>, cudaFuncAttributeMaxDynamicSharedMemorySize, SM);
    cudaFuncSetAttribute(gemm_tc<3,false,true>, cudaFuncAttributeMaxDynamicSharedMemorySize, SM);
    cudaFuncSetAttribute(gemm_tc<2,true,false>, cudaFuncAttributeMaxDynamicSharedMemorySize, SM);

    // #1-#3
    convert_split8<<<(4096*1024/8+255)/256, 256>>>(in_proj_w, 1024, 1024, WinS, 4096*1024/8);
    convert_split8<<<(96*2048/8+255)/256,   256>>>(x_proj_w,  2048, 2048, WxpS, 96*2048/8);
    rmsnorm_split_kernel<<<NTOK, 256>>>(hidden, norm1_w, uS);

    // #4: in_proj GEMM (ncu profile target)
    gemm_tc<0,false,true><<<dim3(296,1,1), 256, SM>>>(
        uS, WinS, 1024, 1024, 4096, nullptr, xz, 2*DI, nullptr);

    // remaining weight converts
    convert_split8<<<(2048*64/8+255)/256,   256>>>(dt_proj_w, 64,   64,   WdtS, 2048*64/8);
    convert_split8<<<(1024*2048/8+255)/256, 256>>>(out_proj_w,2048, 2048, WoutS,1024*2048/8);
    convert_split8<<<(4096*1024/8+255)/256, 256>>>(fc1_w, 1024, 1024, Wfc1S, 4096*1024/8);
    convert_split8<<<(1024*4096/8+255)/256, 256>>>(fc2_w, 4096, 4096, Wfc2S, 1024*4096/8);

    // conv + silu
    conv_silu_kernel<<<(NTOK*DI/4+255)/256, 256>>>(xz, conv_w, conv_b, xc, xcS);

    // x_proj split-K=8 -> partials -> xdbl
    gemm_tc<0,false,true><<<dim3(16,1,8), 256, SM>>>(
        xcS, WxpS, 2048, 256, 96, nullptr, part, 96, nullptr);
    reduce_epi<0,true,false><<<(NTOK*96/4+255)/256, 256>>>(
        part, 8, 96, nullptr, nullptr, 0, xdbl, 96, nullptr);

    // split dt_in columns
    convert_split8<<<(NTOK*DTR/8+255)/256, 256>>>(xdbl, 96, DTR, dtAS, NTOK*DTR/8);

    // dt_proj + softplus(+bias)
    gemm_tc<3,false,true><<<dim3(256,1,1), 256, SM>>>(
        dtAS, WdtS, 64, 64, 2048, dt_proj_b, dt, DI, nullptr);

    // selective scan + gating
    scan_kernel<<<(BB*DI*4)/128, 128>>>(dt, xc, xdbl, xz, A_log, D_param, ymS);

    // out_proj split-K=2 + residual(hidden) -> h
    gemm_tc<0,false,true><<<dim3(128,1,2), 256, SM>>>(
        ymS, WoutS, 2048, 1024, 1024, nullptr, part, 1024, nullptr);
    reduce_epi<4,true,false><<<(NTOK*1024/4+255)/256, 256>>>(
        part, 2, 1024, nullptr, hidden, DD, h, DD, nullptr);

    // rmsnorm2
    rmsnorm_split_kernel<<<NTOK, 256>>>(h, norm2_w, hnS);

    // fc1 + bias + silu -> m1 split
    gemm_tc<2,true,false><<<dim3(296,1,1), 256, SM>>>(
        hnS, Wfc1S, 1024, 1024, 4096, fc1_b, nullptr, 0, m1S);

    // fc2 split-K=2 + bias + residual(h) -> out
    gemm_tc<0,false,true><<<dim3(128,1,2), 256, SM>>>(
        m1S, Wfc2S, 4096, 2048, 1024, nullptr, part, 1024, nullptr);
    reduce_epi<5,true,false><<<(NTOK*1024/4+255)/256, 256>>>(
        part, 2, 1024, fc2_b, h, DD, out, DD, nullptr);
}